// round 1
// baseline (speedup 1.0000x reference)
#include <cuda_runtime.h>
#include <math.h>

// Fixed problem shape (VRWKV_SpatialMix_59356448031087 setup_inputs):
// B=8, H=W=64 -> T=4096, C=512, gamma=0.25 -> g=128 (4g == C, no identity slice)
#define BB   8
#define HH   64
#define WW   64
#define TT   4096      // H*W
#define CC   512
#define BTC  (BB*TT*CC)   // 16,777,216

// ---------------- scratch (no dynamic allocation allowed) ----------------
__device__ float g_xi [BTC];   // shifted+zigzag input, later reused for permuted k
__device__ float g_k  [BTC];
__device__ float g_v  [BTC];   // v, then y1 in-place
__device__ float g_sr [BTC];
__device__ float g_tmp[BTC];   // permuted v / y2

// ---------------- kernel 1: q_shift + zigzag gather ----------------
// out token t' reads spatial position zz[t'] of the q-shifted image.
// zigzag(top-left, horizontal): row i, cols forward if i even else reversed.
__global__ void shift_zigzag_kernel(const float* __restrict__ x, float* __restrict__ xi) {
    int gid = blockIdx.x * 256 + threadIdx.x;          // ((b*T)+t')*C + c
    int c  = gid & (CC - 1);
    int tp = (gid >> 9) & (TT - 1);
    int b  = gid >> 21;
    int i  = tp >> 6;
    int jj = tp & 63;
    int col = (i & 1) ? (63 - jj) : jj;
    int h0 = i, w0 = col;
    int grp = c >> 7;                                   // channel quarter
    int hs = h0, ws = w0;
    bool valid;
    if (grp == 0)      { ws = w0 - 1; valid = (w0 >= 1);  }
    else if (grp == 1) { ws = w0 + 1; valid = (w0 <= 62); }
    else if (grp == 2) { hs = h0 - 1; valid = (h0 >= 1);  }
    else               { hs = h0 + 1; valid = (h0 <= 62); }
    float val = valid ? x[((b << 12) + (hs << 6) + ws) * CC + c] : 0.f;
    xi[gid] = val;
}

// ---------------- kernel 2: zigzag permute of k and y1 ----------------
__global__ void permute_kernel(const float* __restrict__ in1, float* __restrict__ out1,
                               const float* __restrict__ in2, float* __restrict__ out2) {
    int gid = blockIdx.x * 256 + threadIdx.x;
    int c  = gid & (CC - 1);
    int tp = (gid >> 9) & (TT - 1);
    int b  = gid >> 21;
    int i  = tp >> 6;
    int jj = tp & 63;
    int col = (i & 1) ? (63 - jj) : jj;
    int src = ((b << 12) + (i << 6) + col) * CC + c;
    out1[gid] = in1[src];
    out2[gid] = in2[src];
}

// ---------------- kernel 3: NT SGEMM  Y = f(A (*A2) @ W^T) ----------------
// A: [M=32768, K=512] row-major. W: [N=512, K=512] row-major. Y: [M, N].
// FLAG 0: plain, 1: sigmoid epilogue, 2: A multiplied elementwise by A2.
// Tiles 128x128x16, 256 threads, 8x8 microtile per thread.
#define GM 32768
#define GN 512
#define GK 512

template<int FLAG>
__global__ __launch_bounds__(256) void sgemm_nt(const float* __restrict__ A,
                                                const float* __restrict__ A2,
                                                const float* __restrict__ Bw,
                                                float* __restrict__ Co) {
    __shared__ float As[16][128];
    __shared__ float Bs[16][128];
    const int m0 = blockIdx.y * 128;
    const int n0 = blockIdx.x * 128;
    const int tid = threadIdx.x;
    const int lr = tid >> 2;            // 0..63 (tile row)
    const int lc = (tid & 3) << 2;      // 0,4,8,12 (k offset)
    const int tx = tid & 15;            // n micro 0..15
    const int ty = tid >> 4;            // m micro 0..15

    float acc[8][8];
    #pragma unroll
    for (int i = 0; i < 8; i++)
        #pragma unroll
        for (int j = 0; j < 8; j++) acc[i][j] = 0.f;

    const float* Aptr  = A  + (m0 + lr) * GK + lc;
    const float* A2ptr = (FLAG == 2) ? (A2 + (m0 + lr) * GK + lc) : A;
    const float* Bptr  = Bw + (n0 + lr) * GK + lc;

    for (int kt = 0; kt < GK; kt += 16) {
        float4 a0 = *(const float4*)(Aptr + kt);
        float4 a1 = *(const float4*)(Aptr + 64 * GK + kt);
        float4 b0 = *(const float4*)(Bptr + kt);
        float4 b1 = *(const float4*)(Bptr + 64 * GK + kt);
        if (FLAG == 2) {
            float4 c0 = *(const float4*)(A2ptr + kt);
            float4 c1 = *(const float4*)(A2ptr + 64 * GK + kt);
            a0.x *= c0.x; a0.y *= c0.y; a0.z *= c0.z; a0.w *= c0.w;
            a1.x *= c1.x; a1.y *= c1.y; a1.z *= c1.z; a1.w *= c1.w;
        }
        As[lc + 0][lr] = a0.x; As[lc + 1][lr] = a0.y;
        As[lc + 2][lr] = a0.z; As[lc + 3][lr] = a0.w;
        As[lc + 0][lr + 64] = a1.x; As[lc + 1][lr + 64] = a1.y;
        As[lc + 2][lr + 64] = a1.z; As[lc + 3][lr + 64] = a1.w;
        Bs[lc + 0][lr] = b0.x; Bs[lc + 1][lr] = b0.y;
        Bs[lc + 2][lr] = b0.z; Bs[lc + 3][lr] = b0.w;
        Bs[lc + 0][lr + 64] = b1.x; Bs[lc + 1][lr + 64] = b1.y;
        Bs[lc + 2][lr + 64] = b1.z; Bs[lc + 3][lr + 64] = b1.w;
        __syncthreads();

        #pragma unroll
        for (int kk = 0; kk < 16; kk++) {
            float4 ar0 = *(const float4*)&As[kk][ty * 8];
            float4 ar1 = *(const float4*)&As[kk][ty * 8 + 4];
            float4 br0 = *(const float4*)&Bs[kk][tx * 8];
            float4 br1 = *(const float4*)&Bs[kk][tx * 8 + 4];
            float a_[8] = {ar0.x, ar0.y, ar0.z, ar0.w, ar1.x, ar1.y, ar1.z, ar1.w};
            float b_[8] = {br0.x, br0.y, br0.z, br0.w, br1.x, br1.y, br1.z, br1.w};
            #pragma unroll
            for (int i = 0; i < 8; i++)
                #pragma unroll
                for (int j = 0; j < 8; j++)
                    acc[i][j] = fmaf(a_[i], b_[j], acc[i][j]);
        }
        __syncthreads();
    }

    #pragma unroll
    for (int i = 0; i < 8; i++) {
        float* crow = Co + (m0 + ty * 8 + i) * GN + n0 + tx * 8;
        float out[8];
        #pragma unroll
        for (int j = 0; j < 8; j++) {
            float vv = acc[i][j];
            if (FLAG == 1) vv = 1.f / (1.f + __expf(-vv));
            out[j] = vv;
        }
        *(float4*)(crow)     = make_float4(out[0], out[1], out[2], out[3]);
        *(float4*)(crow + 4) = make_float4(out[4], out[5], out[6], out[7]);
    }
}

// ---------------- kernel 4: WKV scan (RWKV-v4, numerically stable) --------
// One thread per (b, c); sequential over T. y may alias v (write-after-read).
__global__ void wkv_kernel(const float* __restrict__ decay, const float* __restrict__ first,
                           int j, const float* __restrict__ K, const float* __restrict__ V,
                           float* __restrict__ Y) {
    int gid = blockIdx.x * blockDim.x + threadIdx.x;
    if (gid >= BB * CC) return;
    int b = gid >> 9;
    int c = gid & (CC - 1);
    const float inv_t = 1.0f / (float)TT;
    float w = decay[j * CC + c] * inv_t;
    float u = first[j * CC + c] * inv_t;
    float p = 0.f, q = 0.f, o = -1e38f;
    int base = (b << 12) * CC + c;
    for (int t = 0; t < TT; t++) {
        int idx = base + t * CC;
        float kt = K[idx];
        float vt = V[idx];
        float no = fmaxf(o, u + kt);
        float Aa = __expf(o - no);
        float Bq = __expf(u + kt - no);
        float y = fmaf(Aa, p, Bq * vt) / fmaf(Aa, q, Bq);
        Y[idx] = y;
        float no2 = fmaxf(w + o, kt);
        float A2 = __expf(w + o - no2);
        float B2 = __expf(kt - no2);
        p = fmaf(A2, p, B2 * vt);
        q = fmaf(A2, q, B2);
        o = no2;
    }
}

// ---------------- launch ----------------
extern "C" void kernel_launch(void* const* d_in, const int* in_sizes, int n_in,
                              void* d_out, int out_size) {
    const float* x       = (const float*)d_in[0];
    const float* W_key   = (const float*)d_in[1];
    const float* W_value = (const float*)d_in[2];
    const float* W_recep = (const float*)d_in[3];
    const float* W_out   = (const float*)d_in[4];
    const float* decay   = (const float*)d_in[5];
    const float* first   = (const float*)d_in[6];
    float* out = (float*)d_out;

    float *xi, *k, *v, *sr, *tmp;
    cudaGetSymbolAddress((void**)&xi,  g_xi);
    cudaGetSymbolAddress((void**)&k,   g_k);
    cudaGetSymbolAddress((void**)&v,   g_v);
    cudaGetSymbolAddress((void**)&sr,  g_sr);
    cudaGetSymbolAddress((void**)&tmp, g_tmp);

    dim3 eb(256), eg(BTC / 256);
    dim3 gb(256), gg(GN / 128, GM / 128);

    // 1) q_shift + zigzag
    shift_zigzag_kernel<<<eg, eb>>>(x, xi);
    // 2) k, v, sr
    sgemm_nt<0><<<gg, gb>>>(xi, nullptr, W_key,   k);
    sgemm_nt<0><<<gg, gb>>>(xi, nullptr, W_value, v);
    sgemm_nt<1><<<gg, gb>>>(xi, nullptr, W_recep, sr);
    // 3) wkv j=0 (y1 in-place over v)
    wkv_kernel<<<(BB * CC + 31) / 32, 32>>>(decay, first, 0, k, v, v);
    // 4) permute k -> xi (reuse), y1 -> tmp
    permute_kernel<<<eg, eb>>>(k, xi, v, tmp);
    // 5) wkv j=1 (y2 in-place over tmp)
    wkv_kernel<<<(BB * CC + 31) / 32, 32>>>(decay, first, 1, xi, tmp, tmp);
    // 6) (sr * y2) @ W_out^T
    sgemm_nt<2><<<gg, gb>>>(tmp, sr, W_out, out);
}

// round 2
// speedup vs baseline: 3.0934x; 3.0934x over previous
#include <cuda_runtime.h>
#include <math.h>

// Fixed problem shape: B=8, H=W=64 -> T=4096, C=512, gamma=0.25 -> g=128 (4g==C)
#define BB   8
#define TT   4096
#define CC   512
#define BTC  (BB*TT*CC)

// ---------------- scratch ----------------
__device__ float g_xi [BTC];
__device__ float g_k  [BTC];
__device__ float g_v  [BTC];
__device__ float g_sr [BTC];
__device__ float g_tmp[BTC];

// ---------------- kernel 1: q_shift + zigzag gather ----------------
__global__ void shift_zigzag_kernel(const float* __restrict__ x, float* __restrict__ xi) {
    int gid = blockIdx.x * 256 + threadIdx.x;
    int c  = gid & (CC - 1);
    int tp = (gid >> 9) & (TT - 1);
    int b  = gid >> 21;
    int i  = tp >> 6;
    int jj = tp & 63;
    int col = (i & 1) ? (63 - jj) : jj;
    int grp = c >> 7;
    int hs = i, ws = col;
    bool valid;
    if (grp == 0)      { ws = col - 1; valid = (col >= 1);  }
    else if (grp == 1) { ws = col + 1; valid = (col <= 62); }
    else if (grp == 2) { hs = i - 1;   valid = (i >= 1);    }
    else               { hs = i + 1;   valid = (i <= 62);   }
    xi[gid] = valid ? x[((b << 12) + (hs << 6) + ws) * CC + c] : 0.f;
}

// ---------------- kernel 2: zigzag permute of k and y1 ----------------
__global__ void permute_kernel(const float* __restrict__ in1, float* __restrict__ out1,
                               const float* __restrict__ in2, float* __restrict__ out2) {
    int gid = blockIdx.x * 256 + threadIdx.x;
    int c  = gid & (CC - 1);
    int tp = (gid >> 9) & (TT - 1);
    int b  = gid >> 21;
    int i  = tp >> 6;
    int jj = tp & 63;
    int col = (i & 1) ? (63 - jj) : jj;
    int src = ((b << 12) + (i << 6) + col) * CC + c;
    out1[gid] = in1[src];
    out2[gid] = in2[src];
}

// ---------------- kernel 3: NT SGEMM ----------------
#define GM 32768
#define GN 512
#define GK 512

template<int FLAG>
__global__ __launch_bounds__(256) void sgemm_nt(const float* __restrict__ A,
                                                const float* __restrict__ A2,
                                                const float* __restrict__ Bw,
                                                float* __restrict__ Co) {
    __shared__ float As[16][128];
    __shared__ float Bs[16][128];
    const int m0 = blockIdx.y * 128;
    const int n0 = blockIdx.x * 128;
    const int tid = threadIdx.x;
    const int lr = tid >> 2;
    const int lc = (tid & 3) << 2;
    const int tx = tid & 15;
    const int ty = tid >> 4;

    float acc[8][8];
    #pragma unroll
    for (int i = 0; i < 8; i++)
        #pragma unroll
        for (int j = 0; j < 8; j++) acc[i][j] = 0.f;

    const float* Aptr  = A  + (m0 + lr) * GK + lc;
    const float* A2ptr = (FLAG == 2) ? (A2 + (m0 + lr) * GK + lc) : A;
    const float* Bptr  = Bw + (n0 + lr) * GK + lc;

    for (int kt = 0; kt < GK; kt += 16) {
        float4 a0 = *(const float4*)(Aptr + kt);
        float4 a1 = *(const float4*)(Aptr + 64 * GK + kt);
        float4 b0 = *(const float4*)(Bptr + kt);
        float4 b1 = *(const float4*)(Bptr + 64 * GK + kt);
        if (FLAG == 2) {
            float4 c0 = *(const float4*)(A2ptr + kt);
            float4 c1 = *(const float4*)(A2ptr + 64 * GK + kt);
            a0.x *= c0.x; a0.y *= c0.y; a0.z *= c0.z; a0.w *= c0.w;
            a1.x *= c1.x; a1.y *= c1.y; a1.z *= c1.z; a1.w *= c1.w;
        }
        As[lc + 0][lr] = a0.x; As[lc + 1][lr] = a0.y;
        As[lc + 2][lr] = a0.z; As[lc + 3][lr] = a0.w;
        As[lc + 0][lr + 64] = a1.x; As[lc + 1][lr + 64] = a1.y;
        As[lc + 2][lr + 64] = a1.z; As[lc + 3][lr + 64] = a1.w;
        Bs[lc + 0][lr] = b0.x; Bs[lc + 1][lr] = b0.y;
        Bs[lc + 2][lr] = b0.z; Bs[lc + 3][lr] = b0.w;
        Bs[lc + 0][lr + 64] = b1.x; Bs[lc + 1][lr + 64] = b1.y;
        Bs[lc + 2][lr + 64] = b1.z; Bs[lc + 3][lr + 64] = b1.w;
        __syncthreads();

        #pragma unroll
        for (int kk = 0; kk < 16; kk++) {
            float4 ar0 = *(const float4*)&As[kk][ty * 8];
            float4 ar1 = *(const float4*)&As[kk][ty * 8 + 4];
            float4 br0 = *(const float4*)&Bs[kk][tx * 8];
            float4 br1 = *(const float4*)&Bs[kk][tx * 8 + 4];
            float a_[8] = {ar0.x, ar0.y, ar0.z, ar0.w, ar1.x, ar1.y, ar1.z, ar1.w};
            float b_[8] = {br0.x, br0.y, br0.z, br0.w, br1.x, br1.y, br1.z, br1.w};
            #pragma unroll
            for (int i = 0; i < 8; i++)
                #pragma unroll
                for (int j = 0; j < 8; j++)
                    acc[i][j] = fmaf(a_[i], b_[j], acc[i][j]);
        }
        __syncthreads();
    }

    #pragma unroll
    for (int i = 0; i < 8; i++) {
        float* crow = Co + (m0 + ty * 8 + i) * GN + n0 + tx * 8;
        float out[8];
        #pragma unroll
        for (int j = 0; j < 8; j++) {
            float vv = acc[i][j];
            if (FLAG == 1) vv = 1.f / (1.f + __expf(-vv));
            out[j] = vv;
        }
        *(float4*)(crow)     = make_float4(out[0], out[1], out[2], out[3]);
        *(float4*)(crow + 4) = make_float4(out[4], out[5], out[6], out[7]);
    }
}

// ---------------- kernel 4: chunk-parallel WKV scan ----------------
// Block: 16 channels x 32 chunks = 512 threads. Grid: B * (C/16) = 256 blocks.
// The WKV update is state' = stable_add(decay(state, w), point(k,v)) with
// (p,q,o) scaled-triple representation; decay distributes over stable_add,
// so chunk-fold + prefix-combine + replay is FP-equivalent to the serial scan.
#define NCHUNK 32
#define CHL    (TT / NCHUNK)   // 128
#define CPB    16              // channels per block

__global__ __launch_bounds__(512) void wkv_chunked(const float* __restrict__ decay,
                                                   const float* __restrict__ first, int j,
                                                   const float* __restrict__ K,
                                                   const float* __restrict__ V,
                                                   float* __restrict__ Y) {
    __shared__ float sp[NCHUNK][CPB + 1];
    __shared__ float sq[NCHUNK][CPB + 1];
    __shared__ float so[NCHUNK][CPB + 1];
    const int tid = threadIdx.x;
    const int cl = tid & (CPB - 1);       // channel lane
    const int ch = tid / CPB;             // chunk id
    const int cg = blockIdx.x & 31;       // channel group
    const int b  = blockIdx.x >> 5;
    const int c  = cg * CPB + cl;
    const float inv_t = 1.0f / (float)TT;
    const float w = decay[j * CC + c] * inv_t;
    const float u = first[j * CC + c] * inv_t;

    const size_t base = ((size_t)(b * TT + ch * CHL)) * CC + c;

    // ---- pass 1: fold chunk from identity ----
    float p = 0.f, q = 0.f, o = -1e38f;
    #pragma unroll 4
    for (int s = 0; s < CHL; s++) {
        float kt = K[base + (size_t)s * CC];
        float vt = V[base + (size_t)s * CC];
        float no = fmaxf(w + o, kt);
        float A  = __expf(w + o - no);
        float Bv = __expf(kt - no);
        p = fmaf(A, p, Bv * vt);
        q = fmaf(A, q, Bv);
        o = no;
    }
    sp[ch][cl] = p; sq[ch][cl] = q; so[ch][cl] = o;
    __syncthreads();

    // ---- exclusive prefix scan over chunks (16 threads, 32 steps each) ----
    if (ch == 0) {
        const float Lw = (float)CHL * w;
        float ap = 0.f, aq = 0.f, ao = -1e38f;
        #pragma unroll
        for (int i = 0; i < NCHUNK; i++) {
            float tp = sp[i][cl], tq = sq[i][cl], to = so[i][cl];
            sp[i][cl] = ap; sq[i][cl] = aq; so[i][cl] = ao;
            float od = ao + Lw;
            float no = fmaxf(od, to);
            float e1 = __expf(od - no), e2 = __expf(to - no);
            ap = fmaf(e1, ap, e2 * tp);
            aq = fmaf(e1, aq, e2 * tq);
            ao = no;
        }
    }
    __syncthreads();
    p = sp[ch][cl]; q = sq[ch][cl]; o = so[ch][cl];

    // ---- pass 2: replay chunk with prefix state, emit y ----
    #pragma unroll 4
    for (int s = 0; s < CHL; s++) {
        size_t idx = base + (size_t)s * CC;
        float kt = K[idx];
        float vt = V[idx];
        float no = fmaxf(o, u + kt);
        float A  = __expf(o - no);
        float Bv = __expf(u + kt - no);
        float y  = fmaf(A, p, Bv * vt) / fmaf(A, q, Bv);
        Y[idx] = y;
        float no2 = fmaxf(w + o, kt);
        float A2 = __expf(w + o - no2);
        float B2 = __expf(kt - no2);
        p = fmaf(A2, p, B2 * vt);
        q = fmaf(A2, q, B2);
        o = no2;
    }
}

// ---------------- launch ----------------
extern "C" void kernel_launch(void* const* d_in, const int* in_sizes, int n_in,
                              void* d_out, int out_size) {
    const float* x       = (const float*)d_in[0];
    const float* W_key   = (const float*)d_in[1];
    const float* W_value = (const float*)d_in[2];
    const float* W_recep = (const float*)d_in[3];
    const float* W_out   = (const float*)d_in[4];
    const float* decay   = (const float*)d_in[5];
    const float* first   = (const float*)d_in[6];
    float* out = (float*)d_out;

    float *xi, *k, *v, *sr, *tmp;
    cudaGetSymbolAddress((void**)&xi,  g_xi);
    cudaGetSymbolAddress((void**)&k,   g_k);
    cudaGetSymbolAddress((void**)&v,   g_v);
    cudaGetSymbolAddress((void**)&sr,  g_sr);
    cudaGetSymbolAddress((void**)&tmp, g_tmp);

    dim3 eb(256), eg(BTC / 256);
    dim3 gb(256), gg(GN / 128, GM / 128);
    dim3 wb(512), wg(BB * (CC / CPB));   // 256 blocks

    shift_zigzag_kernel<<<eg, eb>>>(x, xi);
    sgemm_nt<0><<<gg, gb>>>(xi, nullptr, W_key,   k);
    sgemm_nt<0><<<gg, gb>>>(xi, nullptr, W_value, v);
    sgemm_nt<1><<<gg, gb>>>(xi, nullptr, W_recep, sr);
    wkv_chunked<<<wg, wb>>>(decay, first, 0, k, v, v);
    permute_kernel<<<eg, eb>>>(k, xi, v, tmp);
    wkv_chunked<<<wg, wb>>>(decay, first, 1, xi, tmp, tmp);
    sgemm_nt<2><<<gg, gb>>>(tmp, sr, W_out, out);
}

// round 4
// speedup vs baseline: 3.2905x; 1.0637x over previous
#include <cuda_runtime.h>
#include <math.h>
#include <stdint.h>

// Fixed problem shape: B=8, H=W=64 -> T=4096, C=512
#define BB   8
#define TT   4096
#define CC   512
#define BTC  (BB*TT*CC)

// ---------------- scratch ----------------
__device__ float g_b1[BTC];   // xi, later y1-permuted (y2 in place)
__device__ float g_b2[BTC];   // k
__device__ float g_b3[BTC];   // v -> y1 in place
__device__ float g_b4[BTC];   // sr
__device__ float g_b5[BTC];   // k permuted

// ---------------- kernel 1: q_shift + zigzag gather (float4) ----------------
// 4 consecutive channels share the same quarter (g=128), so one shift per float4.
__global__ void shift_zigzag_v4(const float* __restrict__ x, float* __restrict__ xi) {
    int gid = blockIdx.x * 256 + threadIdx.x;       // index in float4 units
    int c4 = gid & 127;                              // float4 lane within C (C/4=128)
    int tp = (gid >> 7) & (TT - 1);
    int b  = gid >> 19;
    int i  = tp >> 6;
    int jj = tp & 63;
    int col = (i & 1) ? (63 - jj) : jj;
    int grp = c4 >> 5;                               // quarter (128/4=32 float4s per quarter)
    int hs = i, ws = col;
    bool valid;
    if (grp == 0)      { ws = col - 1; valid = (col >= 1);  }
    else if (grp == 1) { ws = col + 1; valid = (col <= 62); }
    else if (grp == 2) { hs = i - 1;   valid = (i >= 1);    }
    else               { hs = i + 1;   valid = (i <= 62);   }
    float4 v = make_float4(0.f, 0.f, 0.f, 0.f);
    if (valid)
        v = *(const float4*)(x + ((size_t)((b << 12) + (hs << 6) + ws) << 9) + (c4 << 2));
    *(float4*)(xi + ((size_t)gid << 2)) = v;
}

// ---------------- kernel 2: zigzag permute of k and y1 (float4) ----------------
__global__ void permute_v4(const float* __restrict__ in1, float* __restrict__ out1,
                           const float* __restrict__ in2, float* __restrict__ out2) {
    int gid = blockIdx.x * 256 + threadIdx.x;       // float4 units
    int c4 = gid & 127;
    int tp = (gid >> 7) & (TT - 1);
    int b  = gid >> 19;
    int i  = tp >> 6;
    int jj = tp & 63;
    int col = (i & 1) ? (63 - jj) : jj;
    size_t src = ((size_t)((b << 12) + (i << 6) + col) << 9) + (c4 << 2);
    size_t dst = (size_t)gid << 2;
    *(float4*)(out1 + dst) = *(const float4*)(in1 + src);
    *(float4*)(out2 + dst) = *(const float4*)(in2 + src);
}

// ---------------- SGEMM core: 128x128x16 tiles, double-buffered, 1 sync/iter --
#define GM 32768
#define GN 512
#define GK 512

// Core computes C[tile] = A @ Bw^T with optional A2 elementwise multiply and
// optional sigmoid epilogue (runtime flags; uniform per block).
__device__ __forceinline__ void sgemm_core(const float* __restrict__ A,
                                           const float* __restrict__ A2,
                                           const float* __restrict__ Bw,
                                           float* __restrict__ Co,
                                           int m0, int n0, bool mulA2, bool sigm,
                                           float (*As)[16][128], float (*Bs)[16][128]) {
    const int tid = threadIdx.x;
    const int lr = tid >> 2;            // 0..63
    const int lc = (tid & 3) << 2;      // 0,4,8,12
    const int tx = tid & 15;
    const int ty = tid >> 4;

    float acc[8][8];
    #pragma unroll
    for (int i = 0; i < 8; i++)
        #pragma unroll
        for (int j = 0; j < 8; j++) acc[i][j] = 0.f;

    const float* Aptr  = A  + (size_t)(m0 + lr) * GK + lc;
    const float* A2ptr = A2 + (size_t)(m0 + lr) * GK + lc;
    const float* Bptr  = Bw + (size_t)(n0 + lr) * GK + lc;

    float4 a0, a1, b0, b1;
    // prime stage 0
    a0 = *(const float4*)(Aptr);
    a1 = *(const float4*)(Aptr + 64 * GK);
    b0 = *(const float4*)(Bptr);
    b1 = *(const float4*)(Bptr + 64 * GK);
    if (mulA2) {
        float4 c0 = *(const float4*)(A2ptr);
        float4 c1 = *(const float4*)(A2ptr + 64 * GK);
        a0.x *= c0.x; a0.y *= c0.y; a0.z *= c0.z; a0.w *= c0.w;
        a1.x *= c1.x; a1.y *= c1.y; a1.z *= c1.z; a1.w *= c1.w;
    }
    As[0][lc + 0][lr] = a0.x; As[0][lc + 1][lr] = a0.y;
    As[0][lc + 2][lr] = a0.z; As[0][lc + 3][lr] = a0.w;
    As[0][lc + 0][lr + 64] = a1.x; As[0][lc + 1][lr + 64] = a1.y;
    As[0][lc + 2][lr + 64] = a1.z; As[0][lc + 3][lr + 64] = a1.w;
    Bs[0][lc + 0][lr] = b0.x; Bs[0][lc + 1][lr] = b0.y;
    Bs[0][lc + 2][lr] = b0.z; Bs[0][lc + 3][lr] = b0.w;
    Bs[0][lc + 0][lr + 64] = b1.x; Bs[0][lc + 1][lr + 64] = b1.y;
    Bs[0][lc + 2][lr + 64] = b1.z; Bs[0][lc + 3][lr + 64] = b1.w;
    __syncthreads();

    #pragma unroll 1
    for (int kt = 0; kt < 32; kt++) {
        const int s = kt & 1;
        const bool more = (kt + 1 < 32);
        if (more) {
            int ko = (kt + 1) * 16;
            a0 = *(const float4*)(Aptr + ko);
            a1 = *(const float4*)(Aptr + 64 * GK + ko);
            b0 = *(const float4*)(Bptr + ko);
            b1 = *(const float4*)(Bptr + 64 * GK + ko);
            if (mulA2) {
                float4 c0 = *(const float4*)(A2ptr + ko);
                float4 c1 = *(const float4*)(A2ptr + 64 * GK + ko);
                a0.x *= c0.x; a0.y *= c0.y; a0.z *= c0.z; a0.w *= c0.w;
                a1.x *= c1.x; a1.y *= c1.y; a1.z *= c1.z; a1.w *= c1.w;
            }
        }
        #pragma unroll
        for (int kk = 0; kk < 16; kk++) {
            float4 ar0 = *(const float4*)&As[s][kk][ty * 8];
            float4 ar1 = *(const float4*)&As[s][kk][ty * 8 + 4];
            float4 br0 = *(const float4*)&Bs[s][kk][tx * 8];
            float4 br1 = *(const float4*)&Bs[s][kk][tx * 8 + 4];
            float a_[8] = {ar0.x, ar0.y, ar0.z, ar0.w, ar1.x, ar1.y, ar1.z, ar1.w};
            float b_[8] = {br0.x, br0.y, br0.z, br0.w, br1.x, br1.y, br1.z, br1.w};
            #pragma unroll
            for (int i = 0; i < 8; i++)
                #pragma unroll
                for (int j = 0; j < 8; j++)
                    acc[i][j] = fmaf(a_[i], b_[j], acc[i][j]);
        }
        if (more) {
            const int d = s ^ 1;
            As[d][lc + 0][lr] = a0.x; As[d][lc + 1][lr] = a0.y;
            As[d][lc + 2][lr] = a0.z; As[d][lc + 3][lr] = a0.w;
            As[d][lc + 0][lr + 64] = a1.x; As[d][lc + 1][lr + 64] = a1.y;
            As[d][lc + 2][lr + 64] = a1.z; As[d][lc + 3][lr + 64] = a1.w;
            Bs[d][lc + 0][lr] = b0.x; Bs[d][lc + 1][lr] = b0.y;
            Bs[d][lc + 2][lr] = b0.z; Bs[d][lc + 3][lr] = b0.w;
            Bs[d][lc + 0][lr + 64] = b1.x; Bs[d][lc + 1][lr + 64] = b1.y;
            Bs[d][lc + 2][lr + 64] = b1.z; Bs[d][lc + 3][lr + 64] = b1.w;
            __syncthreads();
        }
    }

    #pragma unroll
    for (int i = 0; i < 8; i++) {
        float* crow = Co + (size_t)(m0 + ty * 8 + i) * GN + n0 + tx * 8;
        float out[8];
        #pragma unroll
        for (int j = 0; j < 8; j++) {
            float vv = acc[i][j];
            if (sigm) vv = 1.f / (1.f + __expf(-vv));
            out[j] = vv;
        }
        *(float4*)(crow)     = make_float4(out[0], out[1], out[2], out[3]);
        *(float4*)(crow + 4) = make_float4(out[4], out[5], out[6], out[7]);
    }
}

// Fused k|v|sr GEMM: grid (12, 256); blockIdx.x>>2 selects weight/output.
__global__ __launch_bounds__(256) void sgemm3(const float* __restrict__ A,
                                              const float* __restrict__ Wk,
                                              const float* __restrict__ Wv,
                                              const float* __restrict__ Wr,
                                              float* __restrict__ Ko,
                                              float* __restrict__ Vo,
                                              float* __restrict__ So) {
    __shared__ float As[2][16][128];
    __shared__ float Bs[2][16][128];
    const int which = blockIdx.x >> 2;
    const int n0 = (blockIdx.x & 3) * 128;
    const int m0 = blockIdx.y * 128;
    const float* Bw = (which == 0) ? Wk : (which == 1) ? Wv : Wr;
    float* Co = (which == 0) ? Ko : (which == 1) ? Vo : So;
    sgemm_core(A, A, Bw, Co, m0, n0, false, which == 2, As, Bs);
}

// Final GEMM: (sr * y2) @ W_out^T with inline elementwise multiply.
__global__ __launch_bounds__(256) void sgemm_final(const float* __restrict__ A,
                                                   const float* __restrict__ A2,
                                                   const float* __restrict__ Bw,
                                                   float* __restrict__ Co) {
    __shared__ float As[2][16][128];
    __shared__ float Bs[2][16][128];
    sgemm_core(A, A2, Bw, Co, blockIdx.y * 128, blockIdx.x * 128, true, false, As, Bs);
}

// ---------------- kernel 4: chunk-parallel WKV scan ----------------
#define NCHUNK 32
#define CHL (TT / NCHUNK)
#define CPB 16

__global__ __launch_bounds__(512) void wkv_chunked(const float* __restrict__ decay,
                                                   const float* __restrict__ first, int j,
                                                   const float* __restrict__ K,
                                                   const float* __restrict__ V,
                                                   float* __restrict__ Y) {
    __shared__ float sp[NCHUNK][CPB + 1];
    __shared__ float sq[NCHUNK][CPB + 1];
    __shared__ float so[NCHUNK][CPB + 1];
    const int tid = threadIdx.x;
    const int cl = tid & (CPB - 1);
    const int ch = tid / CPB;
    const int cg = blockIdx.x & 31;
    const int b  = blockIdx.x >> 5;
    const int c  = cg * CPB + cl;
    const float inv_t = 1.0f / (float)TT;
    const float w = decay[j * CC + c] * inv_t;
    const float u = first[j * CC + c] * inv_t;
    const size_t base = ((size_t)(b * TT + ch * CHL)) * CC + c;

    float p = 0.f, q = 0.f, o = -1e38f;
    #pragma unroll 4
    for (int s = 0; s < CHL; s++) {
        float kt = K[base + (size_t)s * CC];
        float vt = V[base + (size_t)s * CC];
        float no = fmaxf(w + o, kt);
        float A  = __expf(w + o - no);
        float Bv = __expf(kt - no);
        p = fmaf(A, p, Bv * vt);
        q = fmaf(A, q, Bv);
        o = no;
    }
    sp[ch][cl] = p; sq[ch][cl] = q; so[ch][cl] = o;
    __syncthreads();

    if (ch == 0) {
        const float Lw = (float)CHL * w;
        float ap = 0.f, aq = 0.f, ao = -1e38f;
        #pragma unroll
        for (int i = 0; i < NCHUNK; i++) {
            float tp = sp[i][cl], tq = sq[i][cl], to = so[i][cl];
            sp[i][cl] = ap; sq[i][cl] = aq; so[i][cl] = ao;
            float od = ao + Lw;
            float no = fmaxf(od, to);
            float e1 = __expf(od - no), e2 = __expf(to - no);
            ap = fmaf(e1, ap, e2 * tp);
            aq = fmaf(e1, aq, e2 * tq);
            ao = no;
        }
    }
    __syncthreads();
    p = sp[ch][cl]; q = sq[ch][cl]; o = so[ch][cl];

    #pragma unroll 4
    for (int s = 0; s < CHL; s++) {
        size_t idx = base + (size_t)s * CC;
        float kt = K[idx];
        float vt = V[idx];
        float no = fmaxf(o, u + kt);
        float A  = __expf(o - no);
        float Bv = __expf(u + kt - no);
        Y[idx] = fmaf(A, p, Bv * vt) / fmaf(A, q, Bv);
        float no2 = fmaxf(w + o, kt);
        float A2 = __expf(w + o - no2);
        float B2 = __expf(kt - no2);
        p = fmaf(A2, p, B2 * vt);
        q = fmaf(A2, q, B2);
        o = no2;
    }
}

// ---------------- launch ----------------
extern "C" void kernel_launch(void* const* d_in, const int* in_sizes, int n_in,
                              void* d_out, int out_size) {
    const float* x       = (const float*)d_in[0];
    const float* W_key   = (const float*)d_in[1];
    const float* W_value = (const float*)d_in[2];
    const float* W_recep = (const float*)d_in[3];
    const float* W_out   = (const float*)d_in[4];
    const float* decay   = (const float*)d_in[5];
    const float* first   = (const float*)d_in[6];
    float* out = (float*)d_out;

    float *b1, *b2, *b3, *b4, *b5;
    cudaGetSymbolAddress((void**)&b1, g_b1);
    cudaGetSymbolAddress((void**)&b2, g_b2);
    cudaGetSymbolAddress((void**)&b3, g_b3);
    cudaGetSymbolAddress((void**)&b4, g_b4);
    cudaGetSymbolAddress((void**)&b5, g_b5);

    dim3 eb(256), eg(BTC / 4 / 256);                // float4 elementwise
    dim3 gb(256);
    dim3 gg3(12, GM / 128);                          // fused k|v|sr
    dim3 gg1(GN / 128, GM / 128);                    // final
    dim3 wb(512), wg(BB * (CC / CPB));

    // 1) q_shift + zigzag -> xi (b1)
    shift_zigzag_v4<<<eg, eb>>>(x, b1);
    // 2) fused k (b2), v (b3), sr (b4, sigmoid)
    sgemm3<<<gg3, gb>>>(b1, W_key, W_value, W_recep, b2, b3, b4);
    // 3) wkv j=0: y1 in place over b3
    wkv_chunked<<<wg, wb>>>(decay, first, 0, b2, b3, b3);
    // 4) permute k->b5, y1->b1 (xi dead)
    permute_v4<<<eg, eb>>>(b2, b5, b3, b1);
    // 5) wkv j=1: y2 in place over b1
    wkv_chunked<<<wg, wb>>>(decay, first, 1, b5, b1, b1);
    // 6) (sr * y2) @ W_out^T
    sgemm_final<<<gg1, gb>>>(b1, b4, W_out, out);
}

// round 5
// speedup vs baseline: 6.5997x; 2.0057x over previous
#include <cuda_runtime.h>
#include <cuda_bf16.h>
#include <math.h>
#include <stdint.h>

// Fixed problem shape: B=8, H=W=64 -> T=4096, C=512
#define BB   8
#define TT   4096
#define CC   512
#define BTC  (BB*TT*CC)
#define GM   32768
#define GK   512

// ---------------- scratch ----------------
__device__ float g_k  [BTC];           // k
__device__ float g_v  [BTC];           // v -> y1 in place
__device__ float g_sr [BTC];           // sr
__device__ float g_kp [BTC];           // permuted k
__device__ float g_y2 [BTC];           // permuted y1 -> y2 in place
__device__ __nv_bfloat16 g_ah[BTC];    // GEMM A hi (xi, then sr*y2)
__device__ __nv_bfloat16 g_al[BTC];    // GEMM A lo
__device__ __nv_bfloat16 g_wh[4*CC*CC];
__device__ __nv_bfloat16 g_wl[4*CC*CC];

// ---------------- asm helpers ----------------
__device__ __forceinline__ uint32_t smem_u32(const void* p) {
    uint32_t a;
    asm("{ .reg .u64 t; cvta.to.shared.u64 t, %1; cvt.u32.u64 %0, t; }" : "=r"(a) : "l"(p));
    return a;
}
__device__ __forceinline__ void cp16(uint32_t d, const void* s) {
    asm volatile("cp.async.cg.shared.global [%0], [%1], 16;" :: "r"(d), "l"(s));
}
#define CP_COMMIT() asm volatile("cp.async.commit_group;" ::: "memory")
#define CP_WAIT0()  asm volatile("cp.async.wait_group 0;" ::: "memory")

__device__ __forceinline__ void ldsm4(uint32_t* r, uint32_t a) {
    asm volatile("ldmatrix.sync.aligned.m8n8.x4.shared.b16 {%0,%1,%2,%3}, [%4];"
        : "=r"(r[0]), "=r"(r[1]), "=r"(r[2]), "=r"(r[3]) : "r"(a));
}
__device__ __forceinline__ void mma16816(float* c, const uint32_t* a, const uint32_t* b) {
    asm volatile("mma.sync.aligned.m16n8k16.row.col.f32.bf16.bf16.f32 "
        "{%0,%1,%2,%3}, {%4,%5,%6,%7}, {%8,%9}, {%0,%1,%2,%3};"
        : "+f"(c[0]), "+f"(c[1]), "+f"(c[2]), "+f"(c[3])
        : "r"(a[0]), "r"(a[1]), "r"(a[2]), "r"(a[3]), "r"(b[0]), "r"(b[1]));
}
#define SW64(o) ((o) ^ (((o) >> 3) & 0x30))

__device__ __forceinline__ void split_bf16(float x, __nv_bfloat16& h, __nv_bfloat16& l) {
    h = __float2bfloat16_rn(x);
    l = __float2bfloat16_rn(x - __bfloat162float(h));
}

// ---------------- kernel 1: q_shift + zigzag -> bf16 hi/lo ----------------
__global__ void shift_zigzag_bf16(const float* __restrict__ x,
                                  __nv_bfloat16* __restrict__ ah,
                                  __nv_bfloat16* __restrict__ al) {
    int gid = blockIdx.x * 256 + threadIdx.x;       // float4 units
    int c4 = gid & 127;
    int tp = (gid >> 7) & (TT - 1);
    int b  = gid >> 19;
    int i  = tp >> 6;
    int jj = tp & 63;
    int col = (i & 1) ? (63 - jj) : jj;
    int grp = c4 >> 5;
    int hs = i, ws = col;
    bool valid;
    if (grp == 0)      { ws = col - 1; valid = (col >= 1);  }
    else if (grp == 1) { ws = col + 1; valid = (col <= 62); }
    else if (grp == 2) { hs = i - 1;   valid = (i >= 1);    }
    else               { hs = i + 1;   valid = (i <= 62);   }
    float4 v = make_float4(0.f, 0.f, 0.f, 0.f);
    if (valid)
        v = *(const float4*)(x + ((size_t)((b << 12) + (hs << 6) + ws) << 9) + (c4 << 2));
    __nv_bfloat16 h[4], l[4];
    split_bf16(v.x, h[0], l[0]); split_bf16(v.y, h[1], l[1]);
    split_bf16(v.z, h[2], l[2]); split_bf16(v.w, h[3], l[3]);
    size_t dst = (size_t)gid << 2;
    *(uint2*)(ah + dst) = *(uint2*)h;
    *(uint2*)(al + dst) = *(uint2*)l;
}

// ---------------- kernel 2: weight conversion (all 4 weights) ----------------
__global__ void conv_w4(const float* __restrict__ w0, const float* __restrict__ w1,
                        const float* __restrict__ w2, const float* __restrict__ w3,
                        __nv_bfloat16* __restrict__ wh, __nv_bfloat16* __restrict__ wl) {
    int gid = blockIdx.x * 256 + threadIdx.x;       // element index over 4*C*C
    int sel = gid >> 18;
    int off = gid & (CC * CC - 1);
    const float* src = (sel == 0) ? w0 : (sel == 1) ? w1 : (sel == 2) ? w2 : w3;
    float v = src[off];
    __nv_bfloat16 h, l;
    split_bf16(v, h, l);
    wh[gid] = h; wl[gid] = l;
}

// ---------------- kernel 3: zigzag permute of k and y1 ----------------
__global__ void permute_v4(const float* __restrict__ in1, float* __restrict__ out1,
                           const float* __restrict__ in2, float* __restrict__ out2) {
    int gid = blockIdx.x * 256 + threadIdx.x;
    int c4 = gid & 127;
    int tp = (gid >> 7) & (TT - 1);
    int b  = gid >> 19;
    int i  = tp >> 6;
    int jj = tp & 63;
    int col = (i & 1) ? (63 - jj) : jj;
    size_t src = ((size_t)((b << 12) + (i << 6) + col) << 9) + (c4 << 2);
    size_t dst = (size_t)gid << 2;
    *(float4*)(out1 + dst) = *(const float4*)(in1 + src);
    *(float4*)(out2 + dst) = *(const float4*)(in2 + src);
}

// ---------------- kernel 4: sr*y2 -> bf16 hi/lo ----------------
__global__ void mul_split_bf16(const float* __restrict__ a, const float* __restrict__ b,
                               __nv_bfloat16* __restrict__ ah, __nv_bfloat16* __restrict__ al) {
    int gid = blockIdx.x * 256 + threadIdx.x;
    size_t p = (size_t)gid << 2;
    float4 va = *(const float4*)(a + p);
    float4 vb = *(const float4*)(b + p);
    __nv_bfloat16 h[4], l[4];
    split_bf16(va.x * vb.x, h[0], l[0]);
    split_bf16(va.y * vb.y, h[1], l[1]);
    split_bf16(va.z * vb.z, h[2], l[2]);
    split_bf16(va.w * vb.w, h[3], l[3]);
    *(uint2*)(ah + p) = *(uint2*)h;
    *(uint2*)(al + p) = *(uint2*)l;
}

// ---------------- GEMM: bf16 3-mma split, 128x128 tiles ----------------
#define TILE_B (128 * 64)          // one operand tile: 128 rows x 64B (32 bf16)
#define STG_B  (4 * TILE_B)        // Ah, Al, Bh, Bl
#define SM_TOT (2 * STG_B)         // 65536

__device__ __forceinline__ void gemm_core(const __nv_bfloat16* __restrict__ Ah,
                                          const __nv_bfloat16* __restrict__ Al,
                                          const __nv_bfloat16* __restrict__ Wh,
                                          const __nv_bfloat16* __restrict__ Wl,
                                          float* __restrict__ Co,
                                          int m0, int n0, bool sigm, char* smem) {
    const int tid = threadIdx.x;
    const int wid = tid >> 5;
    const int lane = tid & 31;
    const int wm = (wid & 3) * 32;
    const int wn = (wid >> 2) * 64;
    const uint32_t sb0 = smem_u32(smem);

    float acc[2][8][4];
    #pragma unroll
    for (int i = 0; i < 2; i++)
        #pragma unroll
        for (int j = 0; j < 8; j++)
            #pragma unroll
            for (int q = 0; q < 4; q++) acc[i][j][q] = 0.f;

    auto load_stage = [&](int kc, int s) {
        uint32_t sb = sb0 + s * STG_B;
        #pragma unroll
        for (int i = 0; i < 2; i++) {
            int idx = tid + i * 256;
            int r = idx >> 2, c16 = idx & 3;
            uint32_t off = (uint32_t)(r * 64 + c16 * 16);
            uint32_t sw = SW64(off);
            size_t ga = (size_t)(m0 + r) * GK + kc * 32 + c16 * 8;
            size_t gb = (size_t)(n0 + r) * GK + kc * 32 + c16 * 8;
            cp16(sb + sw,              Ah + ga);
            cp16(sb + TILE_B + sw,     Al + ga);
            cp16(sb + 2 * TILE_B + sw, Wh + gb);
            cp16(sb + 3 * TILE_B + sw, Wl + gb);
        }
    };

    // ldmatrix lane address components
    const int sub = lane >> 3, lrow = lane & 7;

    load_stage(0, 0); CP_COMMIT(); CP_WAIT0(); __syncthreads();

    #pragma unroll 1
    for (int kc = 0; kc < 16; kc++) {
        const int s = kc & 1;
        if (kc + 1 < 16) { load_stage(kc + 1, s ^ 1); CP_COMMIT(); }
        const uint32_t sb = sb0 + s * STG_B;

        #pragma unroll
        for (int k16 = 0; k16 < 2; k16++) {
            const uint32_t kbyte = (uint32_t)(k16 * 32 + (sub >> 1) * 16);
            uint32_t ah[2][4], al[2][4], bh[8][2], bl[8][2];
            #pragma unroll
            for (int mt = 0; mt < 2; mt++) {
                int row = wm + mt * 16 + (sub & 1) * 8 + lrow;
                uint32_t so = SW64((uint32_t)(row * 64) + kbyte);
                ldsm4(ah[mt], sb + so);
                ldsm4(al[mt], sb + TILE_B + so);
            }
            #pragma unroll
            for (int nt = 0; nt < 4; nt++) {
                int row = wn + nt * 16 + (sub & 1) * 8 + lrow;
                uint32_t so = SW64((uint32_t)(row * 64) + kbyte);
                uint32_t t0[4], t1[4];
                ldsm4(t0, sb + 2 * TILE_B + so);
                ldsm4(t1, sb + 3 * TILE_B + so);
                bh[2*nt][0] = t0[0]; bh[2*nt+1][0] = t0[1];
                bh[2*nt][1] = t0[2]; bh[2*nt+1][1] = t0[3];
                bl[2*nt][0] = t1[0]; bl[2*nt+1][0] = t1[1];
                bl[2*nt][1] = t1[2]; bl[2*nt+1][1] = t1[3];
            }
            #pragma unroll
            for (int mt = 0; mt < 2; mt++)
                #pragma unroll
                for (int n8 = 0; n8 < 8; n8++) {
                    mma16816(acc[mt][n8], ah[mt], bh[n8]);
                    mma16816(acc[mt][n8], ah[mt], bl[n8]);
                    mma16816(acc[mt][n8], al[mt], bh[n8]);
                }
        }
        if (kc + 1 < 16) { CP_WAIT0(); __syncthreads(); }
    }

    // epilogue
    const int g = lane >> 2, t = lane & 3;
    #pragma unroll
    for (int mt = 0; mt < 2; mt++) {
        #pragma unroll
        for (int n8 = 0; n8 < 8; n8++) {
            int row0 = m0 + wm + mt * 16 + g;
            int col  = n0 + wn + n8 * 8 + t * 2;
            float c0 = acc[mt][n8][0], c1 = acc[mt][n8][1];
            float c2 = acc[mt][n8][2], c3 = acc[mt][n8][3];
            if (sigm) {
                c0 = 1.f / (1.f + __expf(-c0));
                c1 = 1.f / (1.f + __expf(-c1));
                c2 = 1.f / (1.f + __expf(-c2));
                c3 = 1.f / (1.f + __expf(-c3));
            }
            *(float2*)(Co + (size_t)row0 * CC + col)       = make_float2(c0, c1);
            *(float2*)(Co + (size_t)(row0 + 8) * CC + col) = make_float2(c2, c3);
        }
    }
}

// fused k|v|sr: grid (12, 256)
__global__ __launch_bounds__(256) void gemm3_bf16(const __nv_bfloat16* __restrict__ Ah,
                                                  const __nv_bfloat16* __restrict__ Al,
                                                  const __nv_bfloat16* __restrict__ Wh,
                                                  const __nv_bfloat16* __restrict__ Wl,
                                                  float* __restrict__ Ko,
                                                  float* __restrict__ Vo,
                                                  float* __restrict__ So) {
    extern __shared__ char smem[];
    const int which = blockIdx.x >> 2;
    const int n0 = (blockIdx.x & 3) * 128;
    const int m0 = blockIdx.y * 128;
    float* Co = (which == 0) ? Ko : (which == 1) ? Vo : So;
    gemm_core(Ah, Al, Wh + (size_t)which * CC * CC, Wl + (size_t)which * CC * CC,
              Co, m0, n0, which == 2, smem);
}

// final: grid (4, 256)
__global__ __launch_bounds__(256) void gemm1_bf16(const __nv_bfloat16* __restrict__ Ah,
                                                  const __nv_bfloat16* __restrict__ Al,
                                                  const __nv_bfloat16* __restrict__ Wh,
                                                  const __nv_bfloat16* __restrict__ Wl,
                                                  float* __restrict__ Co) {
    extern __shared__ char smem[];
    gemm_core(Ah, Al, Wh, Wl, Co, blockIdx.y * 128, blockIdx.x * 128, false, smem);
}

// ---------------- kernel: chunk-parallel WKV scan ----------------
#define NCHUNK 32
#define CHL (TT / NCHUNK)
#define CPB 16

__global__ __launch_bounds__(512) void wkv_chunked(const float* __restrict__ decay,
                                                   const float* __restrict__ first, int j,
                                                   const float* __restrict__ K,
                                                   const float* __restrict__ V,
                                                   float* __restrict__ Y) {
    __shared__ float sp[NCHUNK][CPB + 1];
    __shared__ float sq[NCHUNK][CPB + 1];
    __shared__ float so[NCHUNK][CPB + 1];
    const int tid = threadIdx.x;
    const int cl = tid & (CPB - 1);
    const int ch = tid / CPB;
    const int cg = blockIdx.x & 31;
    const int b  = blockIdx.x >> 5;
    const int c  = cg * CPB + cl;
    const float inv_t = 1.0f / (float)TT;
    const float w = decay[j * CC + c] * inv_t;
    const float u = first[j * CC + c] * inv_t;
    const size_t base = ((size_t)(b * TT + ch * CHL)) * CC + c;

    float p = 0.f, q = 0.f, o = -1e38f;
    #pragma unroll 4
    for (int s = 0; s < CHL; s++) {
        float kt = K[base + (size_t)s * CC];
        float vt = V[base + (size_t)s * CC];
        float no = fmaxf(w + o, kt);
        float A  = __expf(w + o - no);
        float Bv = __expf(kt - no);
        p = fmaf(A, p, Bv * vt);
        q = fmaf(A, q, Bv);
        o = no;
    }
    sp[ch][cl] = p; sq[ch][cl] = q; so[ch][cl] = o;
    __syncthreads();

    if (ch == 0) {
        const float Lw = (float)CHL * w;
        float ap = 0.f, aq = 0.f, ao = -1e38f;
        #pragma unroll
        for (int i = 0; i < NCHUNK; i++) {
            float tp = sp[i][cl], tq = sq[i][cl], to = so[i][cl];
            sp[i][cl] = ap; sq[i][cl] = aq; so[i][cl] = ao;
            float od = ao + Lw;
            float no = fmaxf(od, to);
            float e1 = __expf(od - no), e2 = __expf(to - no);
            ap = fmaf(e1, ap, e2 * tp);
            aq = fmaf(e1, aq, e2 * tq);
            ao = no;
        }
    }
    __syncthreads();
    p = sp[ch][cl]; q = sq[ch][cl]; o = so[ch][cl];

    #pragma unroll 4
    for (int s = 0; s < CHL; s++) {
        size_t idx = base + (size_t)s * CC;
        float kt = K[idx];
        float vt = V[idx];
        float no = fmaxf(o, u + kt);
        float A  = __expf(o - no);
        float Bv = __expf(u + kt - no);
        Y[idx] = fmaf(A, p, Bv * vt) / fmaf(A, q, Bv);
        float no2 = fmaxf(w + o, kt);
        float A2 = __expf(w + o - no2);
        float B2 = __expf(kt - no2);
        p = fmaf(A2, p, B2 * vt);
        q = fmaf(A2, q, B2);
        o = no2;
    }
}

// ---------------- launch ----------------
extern "C" void kernel_launch(void* const* d_in, const int* in_sizes, int n_in,
                              void* d_out, int out_size) {
    const float* x       = (const float*)d_in[0];
    const float* W_key   = (const float*)d_in[1];
    const float* W_value = (const float*)d_in[2];
    const float* W_recep = (const float*)d_in[3];
    const float* W_out   = (const float*)d_in[4];
    const float* decay   = (const float*)d_in[5];
    const float* first   = (const float*)d_in[6];
    float* out = (float*)d_out;

    float *k, *v, *sr, *kp, *y2;
    __nv_bfloat16 *ah, *al, *wh, *wl;
    cudaGetSymbolAddress((void**)&k,  g_k);
    cudaGetSymbolAddress((void**)&v,  g_v);
    cudaGetSymbolAddress((void**)&sr, g_sr);
    cudaGetSymbolAddress((void**)&kp, g_kp);
    cudaGetSymbolAddress((void**)&y2, g_y2);
    cudaGetSymbolAddress((void**)&ah, g_ah);
    cudaGetSymbolAddress((void**)&al, g_al);
    cudaGetSymbolAddress((void**)&wh, g_wh);
    cudaGetSymbolAddress((void**)&wl, g_wl);

    cudaFuncSetAttribute(gemm3_bf16, cudaFuncAttributeMaxDynamicSharedMemorySize, SM_TOT);
    cudaFuncSetAttribute(gemm1_bf16, cudaFuncAttributeMaxDynamicSharedMemorySize, SM_TOT);

    dim3 eb(256), eg(BTC / 4 / 256);
    dim3 cg(4 * CC * CC / 256);
    dim3 gb(256), gg3(12, GM / 128), gg1(4, GM / 128);
    dim3 wb(512), wg(BB * (CC / CPB));

    // 1) q_shift + zigzag -> bf16 hi/lo
    shift_zigzag_bf16<<<eg, eb>>>(x, ah, al);
    // 2) convert all 4 weights
    conv_w4<<<cg, eb>>>(W_key, W_value, W_recep, W_out, wh, wl);
    // 3) fused k, v, sr(sigmoid)
    gemm3_bf16<<<gg3, gb, SM_TOT>>>(ah, al, wh, wl, k, v, sr);
    // 4) wkv j=0: y1 in place over v
    wkv_chunked<<<wg, wb>>>(decay, first, 0, k, v, v);
    // 5) permute k->kp, y1->y2
    permute_v4<<<eg, eb>>>(k, kp, v, y2);
    // 6) wkv j=1: y2 in place
    wkv_chunked<<<wg, wb>>>(decay, first, 1, kp, y2, y2);
    // 7) sr*y2 -> bf16 hi/lo (reuse ah/al)
    mul_split_bf16<<<eg, eb>>>(sr, y2, ah, al);
    // 8) final GEMM
    gemm1_bf16<<<gg1, gb, SM_TOT>>>(ah, al, wh + 3 * (size_t)CC * CC, wl + 3 * (size_t)CC * CC, out);
}

// round 6
// speedup vs baseline: 7.8294x; 1.1863x over previous
#include <cuda_runtime.h>
#include <cuda_bf16.h>
#include <math.h>
#include <stdint.h>

// Fixed problem shape: B=8, H=W=64 -> T=4096, C=512
#define BB   8
#define TT   4096
#define CC   512
#define BTC  (BB*TT*CC)
#define GM   32768
#define GK   512

// ---------------- scratch ----------------
__device__ float g_k  [BTC];
__device__ float g_v  [BTC];           // v -> y1 in place
__device__ float g_sr [BTC];
__device__ __nv_bfloat16 g_ah[BTC];    // GEMM A hi (xi, then sr*y2)
__device__ __nv_bfloat16 g_al[BTC];
__device__ __nv_bfloat16 g_wh[4*CC*CC];
__device__ __nv_bfloat16 g_wl[4*CC*CC];

// ---------------- asm helpers ----------------
__device__ __forceinline__ uint32_t smem_u32(const void* p) {
    uint32_t a;
    asm("{ .reg .u64 t; cvta.to.shared.u64 t, %1; cvt.u32.u64 %0, t; }" : "=r"(a) : "l"(p));
    return a;
}
__device__ __forceinline__ void cp16(uint32_t d, const void* s) {
    asm volatile("cp.async.cg.shared.global [%0], [%1], 16;" :: "r"(d), "l"(s));
}
#define CP_COMMIT() asm volatile("cp.async.commit_group;" ::: "memory")
#define CP_WAIT0()  asm volatile("cp.async.wait_group 0;" ::: "memory")
#define CP_WAIT1()  asm volatile("cp.async.wait_group 1;" ::: "memory")

__device__ __forceinline__ void ldsm4(uint32_t* r, uint32_t a) {
    asm volatile("ldmatrix.sync.aligned.m8n8.x4.shared.b16 {%0,%1,%2,%3}, [%4];"
        : "=r"(r[0]), "=r"(r[1]), "=r"(r[2]), "=r"(r[3]) : "r"(a));
}
__device__ __forceinline__ void mma16816(float* c, const uint32_t* a, const uint32_t* b) {
    asm volatile("mma.sync.aligned.m16n8k16.row.col.f32.bf16.bf16.f32 "
        "{%0,%1,%2,%3}, {%4,%5,%6,%7}, {%8,%9}, {%0,%1,%2,%3};"
        : "+f"(c[0]), "+f"(c[1]), "+f"(c[2]), "+f"(c[3])
        : "r"(a[0]), "r"(a[1]), "r"(a[2]), "r"(a[3]), "r"(b[0]), "r"(b[1]));
}
#define SW64(o) ((o) ^ (((o) >> 3) & 0x30))

__device__ __forceinline__ void split_bf16(float x, __nv_bfloat16& h, __nv_bfloat16& l) {
    h = __float2bfloat16_rn(x);
    l = __float2bfloat16_rn(x - __bfloat162float(h));
}

// ---------------- kernel 1: q_shift + zigzag -> bf16 hi/lo ----------------
__global__ void shift_zigzag_bf16(const float* __restrict__ x,
                                  __nv_bfloat16* __restrict__ ah,
                                  __nv_bfloat16* __restrict__ al) {
    int gid = blockIdx.x * 256 + threadIdx.x;       // float4 units
    int c4 = gid & 127;
    int tp = (gid >> 7) & (TT - 1);
    int b  = gid >> 19;
    int i  = tp >> 6;
    int jj = tp & 63;
    int col = (i & 1) ? (63 - jj) : jj;
    int grp = c4 >> 5;
    int hs = i, ws = col;
    bool valid;
    if (grp == 0)      { ws = col - 1; valid = (col >= 1);  }
    else if (grp == 1) { ws = col + 1; valid = (col <= 62); }
    else if (grp == 2) { hs = i - 1;   valid = (i >= 1);    }
    else               { hs = i + 1;   valid = (i <= 62);   }
    float4 v = make_float4(0.f, 0.f, 0.f, 0.f);
    if (valid)
        v = *(const float4*)(x + ((size_t)((b << 12) + (hs << 6) + ws) << 9) + (c4 << 2));
    __nv_bfloat16 h[4], l[4];
    split_bf16(v.x, h[0], l[0]); split_bf16(v.y, h[1], l[1]);
    split_bf16(v.z, h[2], l[2]); split_bf16(v.w, h[3], l[3]);
    size_t dst = (size_t)gid << 2;
    *(uint2*)(ah + dst) = *(uint2*)h;
    *(uint2*)(al + dst) = *(uint2*)l;
}

// ---------------- kernel 2: weight conversion ----------------
__global__ void conv_w4(const float* __restrict__ w0, const float* __restrict__ w1,
                        const float* __restrict__ w2, const float* __restrict__ w3,
                        __nv_bfloat16* __restrict__ wh, __nv_bfloat16* __restrict__ wl) {
    int gid = blockIdx.x * 256 + threadIdx.x;
    int sel = gid >> 18;
    int off = gid & (CC * CC - 1);
    const float* src = (sel == 0) ? w0 : (sel == 1) ? w1 : (sel == 2) ? w2 : w3;
    float v = src[off];
    __nv_bfloat16 h, l;
    split_bf16(v, h, l);
    wh[gid] = h; wl[gid] = l;
}

// ---------------- GEMM: bf16 3-mma split, 128x128 tiles, 3-stage pipe ------
#define TILE_B (128 * 64)
#define STG_B  (4 * TILE_B)        // 32 KB
#define SM_TOT (3 * STG_B)         // 96 KB

__device__ __forceinline__ void gemm_core(const __nv_bfloat16* __restrict__ Ah,
                                          const __nv_bfloat16* __restrict__ Al,
                                          const __nv_bfloat16* __restrict__ Wh,
                                          const __nv_bfloat16* __restrict__ Wl,
                                          float* __restrict__ Co,
                                          int m0, int n0, bool sigm, char* smem) {
    const int tid = threadIdx.x;
    const int wid = tid >> 5;
    const int lane = tid & 31;
    const int wm = (wid & 3) * 32;
    const int wn = (wid >> 2) * 64;
    const uint32_t sb0 = smem_u32(smem);

    float acc[2][8][4];
    #pragma unroll
    for (int i = 0; i < 2; i++)
        #pragma unroll
        for (int j = 0; j < 8; j++)
            #pragma unroll
            for (int q = 0; q < 4; q++) acc[i][j][q] = 0.f;

    auto load_stage = [&](int kc, int s) {
        uint32_t sb = sb0 + s * STG_B;
        #pragma unroll
        for (int i = 0; i < 2; i++) {
            int idx = tid + i * 256;
            int r = idx >> 2, c16 = idx & 3;
            uint32_t sw = SW64((uint32_t)(r * 64 + c16 * 16));
            size_t ga = (size_t)(m0 + r) * GK + kc * 32 + c16 * 8;
            size_t gb = (size_t)(n0 + r) * GK + kc * 32 + c16 * 8;
            cp16(sb + sw,              Ah + ga);
            cp16(sb + TILE_B + sw,     Al + ga);
            cp16(sb + 2 * TILE_B + sw, Wh + gb);
            cp16(sb + 3 * TILE_B + sw, Wl + gb);
        }
    };

    const int sub = lane >> 3, lrow = lane & 7;

    load_stage(0, 0); CP_COMMIT();
    load_stage(1, 1); CP_COMMIT();

    #pragma unroll 1
    for (int kc = 0; kc < 16; kc++) {
        if (kc < 14) { CP_WAIT1(); } else { CP_WAIT0(); }
        __syncthreads();
        if (kc + 2 < 16) {
            int s2 = (kc + 2) % 3;
            load_stage(kc + 2, s2); CP_COMMIT();
        }
        const uint32_t sb = sb0 + (kc % 3) * STG_B;

        #pragma unroll
        for (int k16 = 0; k16 < 2; k16++) {
            const uint32_t kbyte = (uint32_t)(k16 * 32 + (sub >> 1) * 16);
            uint32_t ah[2][4], al[2][4], bh[8][2], bl[8][2];
            #pragma unroll
            for (int mt = 0; mt < 2; mt++) {
                int row = wm + mt * 16 + (sub & 1) * 8 + lrow;
                uint32_t so = SW64((uint32_t)(row * 64) + kbyte);
                ldsm4(ah[mt], sb + so);
                ldsm4(al[mt], sb + TILE_B + so);
            }
            #pragma unroll
            for (int nt = 0; nt < 4; nt++) {
                int row = wn + nt * 16 + (sub & 1) * 8 + lrow;
                uint32_t so = SW64((uint32_t)(row * 64) + kbyte);
                uint32_t t0[4], t1[4];
                ldsm4(t0, sb + 2 * TILE_B + so);
                ldsm4(t1, sb + 3 * TILE_B + so);
                bh[2*nt][0] = t0[0]; bh[2*nt+1][0] = t0[1];
                bh[2*nt][1] = t0[2]; bh[2*nt+1][1] = t0[3];
                bl[2*nt][0] = t1[0]; bl[2*nt+1][0] = t1[1];
                bl[2*nt][1] = t1[2]; bl[2*nt+1][1] = t1[3];
            }
            #pragma unroll
            for (int mt = 0; mt < 2; mt++)
                #pragma unroll
                for (int n8 = 0; n8 < 8; n8++) {
                    mma16816(acc[mt][n8], ah[mt], bh[n8]);
                    mma16816(acc[mt][n8], ah[mt], bl[n8]);
                    mma16816(acc[mt][n8], al[mt], bh[n8]);
                }
        }
    }

    const int g = lane >> 2, t = lane & 3;
    #pragma unroll
    for (int mt = 0; mt < 2; mt++) {
        #pragma unroll
        for (int n8 = 0; n8 < 8; n8++) {
            int row0 = m0 + wm + mt * 16 + g;
            int col  = n0 + wn + n8 * 8 + t * 2;
            float c0 = acc[mt][n8][0], c1 = acc[mt][n8][1];
            float c2 = acc[mt][n8][2], c3 = acc[mt][n8][3];
            if (sigm) {
                c0 = 1.f / (1.f + __expf(-c0));
                c1 = 1.f / (1.f + __expf(-c1));
                c2 = 1.f / (1.f + __expf(-c2));
                c3 = 1.f / (1.f + __expf(-c3));
            }
            *(float2*)(Co + (size_t)row0 * CC + col)       = make_float2(c0, c1);
            *(float2*)(Co + (size_t)(row0 + 8) * CC + col) = make_float2(c2, c3);
        }
    }
}

__global__ __launch_bounds__(256) void gemm3_bf16(const __nv_bfloat16* __restrict__ Ah,
                                                  const __nv_bfloat16* __restrict__ Al,
                                                  const __nv_bfloat16* __restrict__ Wh,
                                                  const __nv_bfloat16* __restrict__ Wl,
                                                  float* __restrict__ Ko,
                                                  float* __restrict__ Vo,
                                                  float* __restrict__ So) {
    extern __shared__ char smem[];
    const int which = blockIdx.x >> 2;
    const int n0 = (blockIdx.x & 3) * 128;
    const int m0 = blockIdx.y * 128;
    float* Co = (which == 0) ? Ko : (which == 1) ? Vo : So;
    gemm_core(Ah, Al, Wh + (size_t)which * CC * CC, Wl + (size_t)which * CC * CC,
              Co, m0, n0, which == 2, smem);
}

__global__ __launch_bounds__(256) void gemm1_bf16(const __nv_bfloat16* __restrict__ Ah,
                                                  const __nv_bfloat16* __restrict__ Al,
                                                  const __nv_bfloat16* __restrict__ Wh,
                                                  const __nv_bfloat16* __restrict__ Wl,
                                                  float* __restrict__ Co) {
    extern __shared__ char smem[];
    gemm_core(Ah, Al, Wh, Wl, Co, blockIdx.y * 128, blockIdx.x * 128, false, smem);
}

// ---------------- WKV scans ----------------
// 1-exp combine trick: no = max(a,b) => one of exp(a-no), exp(b-no) is exactly 1.
#define NCHUNK 64
#define CHL    (TT / NCHUNK)   // 64
#define CPB    16

// scan 1: natural token order, Y (y1) written in place over V.
__global__ __launch_bounds__(1024) void wkv1(const float* __restrict__ decay,
                                             const float* __restrict__ first,
                                             const float* __restrict__ K,
                                             const float* __restrict__ V,
                                             float* __restrict__ Y) {
    __shared__ float sp[NCHUNK][CPB + 1];
    __shared__ float sq[NCHUNK][CPB + 1];
    __shared__ float so[NCHUNK][CPB + 1];
    const int tid = threadIdx.x;
    const int cl = tid & (CPB - 1);
    const int ch = tid / CPB;
    const int cg = blockIdx.x & 31;
    const int b  = blockIdx.x >> 5;
    const int c  = cg * CPB + cl;
    const float inv_t = 1.0f / (float)TT;
    const float w = decay[c] * inv_t;
    const float u = first[c] * inv_t;
    const size_t base = ((size_t)(b * TT + ch * CHL)) * CC + c;

    float p = 0.f, q = 0.f, o = -1e38f;
    #pragma unroll 4
    for (int s = 0; s < CHL; s++) {
        float kt = K[base + (size_t)s * CC];
        float vt = V[base + (size_t)s * CC];
        float wo = w + o;
        float d  = wo - kt;
        float e  = __expf(-fabsf(d));
        bool ge  = (d >= 0.f);
        float A  = ge ? 1.f : e;
        float Bv = ge ? e : 1.f;
        p = fmaf(A, p, Bv * vt);
        q = fmaf(A, q, Bv);
        o = ge ? wo : kt;
    }
    sp[ch][cl] = p; sq[ch][cl] = q; so[ch][cl] = o;
    __syncthreads();

    if (ch == 0) {
        const float Lw = (float)CHL * w;
        float ap = 0.f, aq = 0.f, ao = -1e38f;
        #pragma unroll
        for (int i = 0; i < NCHUNK; i++) {
            float tp = sp[i][cl], tq = sq[i][cl], to = so[i][cl];
            sp[i][cl] = ap; sq[i][cl] = aq; so[i][cl] = ao;
            float od = ao + Lw;
            float d  = od - to;
            float e  = __expf(-fabsf(d));
            bool ge  = (d >= 0.f);
            float e1 = ge ? 1.f : e;
            float e2 = ge ? e : 1.f;
            ap = fmaf(e1, ap, e2 * tp);
            aq = fmaf(e1, aq, e2 * tq);
            ao = ge ? od : to;
        }
    }
    __syncthreads();
    p = sp[ch][cl]; q = sq[ch][cl]; o = so[ch][cl];

    #pragma unroll 4
    for (int s = 0; s < CHL; s++) {
        size_t idx = base + (size_t)s * CC;
        float kt = K[idx];
        float vt = V[idx];
        float uk = u + kt;
        float d1 = o - uk;
        float e1 = __expf(-fabsf(d1));
        bool g1  = (d1 >= 0.f);
        float A1 = g1 ? 1.f : e1;
        float B1 = g1 ? e1 : 1.f;
        Y[idx] = fmaf(A1, p, B1 * vt) / fmaf(A1, q, B1);
        float wo = w + o;
        float d2 = wo - kt;
        float e2 = __expf(-fabsf(d2));
        bool g2  = (d2 >= 0.f);
        float A2 = g2 ? 1.f : e2;
        float B2 = g2 ? e2 : 1.f;
        p = fmaf(A2, p, B2 * vt);
        q = fmaf(A2, q, B2);
        o = g2 ? wo : kt;
    }
}

// scan 2: reads k and y1 at zigzag-gathered rows (fused permute); pass 2 reads
// sr and writes split_bf16(sr * y) directly into the final GEMM's A operands.
__global__ __launch_bounds__(1024) void wkv2(const float* __restrict__ decay,
                                             const float* __restrict__ first,
                                             const float* __restrict__ K,
                                             const float* __restrict__ V,
                                             const float* __restrict__ SR,
                                             __nv_bfloat16* __restrict__ Ah,
                                             __nv_bfloat16* __restrict__ Al) {
    __shared__ float sp[NCHUNK][CPB + 1];
    __shared__ float sq[NCHUNK][CPB + 1];
    __shared__ float so[NCHUNK][CPB + 1];
    const int tid = threadIdx.x;
    const int cl = tid & (CPB - 1);
    const int ch = tid / CPB;          // chunk == image row i (CHL == 64 == W)
    const int cg = blockIdx.x & 31;
    const int b  = blockIdx.x >> 5;
    const int c  = cg * CPB + cl;
    const float inv_t = 1.0f / (float)TT;
    const float w = decay[CC + c] * inv_t;
    const float u = first[CC + c] * inv_t;

    // gather source row: i = ch, col = (i even) ? s : 63 - s
    const bool rev = (ch & 1);
    const size_t brow = ((size_t)(b << 12) + (ch << 6));   // row base (tokens)

    float p = 0.f, q = 0.f, o = -1e38f;
    #pragma unroll 4
    for (int s = 0; s < CHL; s++) {
        int col = rev ? (63 - s) : s;
        size_t idx = (brow + col) * CC + c;
        float kt = K[idx];
        float vt = V[idx];
        float wo = w + o;
        float d  = wo - kt;
        float e  = __expf(-fabsf(d));
        bool ge  = (d >= 0.f);
        float A  = ge ? 1.f : e;
        float Bv = ge ? e : 1.f;
        p = fmaf(A, p, Bv * vt);
        q = fmaf(A, q, Bv);
        o = ge ? wo : kt;
    }
    sp[ch][cl] = p; sq[ch][cl] = q; so[ch][cl] = o;
    __syncthreads();

    if (ch == 0) {
        const float Lw = (float)CHL * w;
        float ap = 0.f, aq = 0.f, ao = -1e38f;
        #pragma unroll
        for (int i = 0; i < NCHUNK; i++) {
            float tp = sp[i][cl], tq = sq[i][cl], to = so[i][cl];
            sp[i][cl] = ap; sq[i][cl] = aq; so[i][cl] = ao;
            float od = ao + Lw;
            float d  = od - to;
            float e  = __expf(-fabsf(d));
            bool ge  = (d >= 0.f);
            float e1 = ge ? 1.f : e;
            float e2 = ge ? e : 1.f;
            ap = fmaf(e1, ap, e2 * tp);
            aq = fmaf(e1, aq, e2 * tq);
            ao = ge ? od : to;
        }
    }
    __syncthreads();
    p = sp[ch][cl]; q = sq[ch][cl]; o = so[ch][cl];

    #pragma unroll 4
    for (int s = 0; s < CHL; s++) {
        int col = rev ? (63 - s) : s;
        size_t idx = (brow + col) * CC + c;                    // gathered source
        size_t odx = ((size_t)(b * TT + ch * CHL + s)) * CC + c;  // output token t'
        float kt = K[idx];
        float vt = V[idx];
        float uk = u + kt;
        float d1 = o - uk;
        float e1 = __expf(-fabsf(d1));
        bool g1  = (d1 >= 0.f);
        float A1 = g1 ? 1.f : e1;
        float B1 = g1 ? e1 : 1.f;
        float y  = fmaf(A1, p, B1 * vt) / fmaf(A1, q, B1);
        float prod = SR[odx] * y;
        __nv_bfloat16 h, l;
        split_bf16(prod, h, l);
        Ah[odx] = h; Al[odx] = l;
        float wo = w + o;
        float d2 = wo - kt;
        float e2 = __expf(-fabsf(d2));
        bool g2  = (d2 >= 0.f);
        float A2 = g2 ? 1.f : e2;
        float B2 = g2 ? e2 : 1.f;
        p = fmaf(A2, p, B2 * vt);
        q = fmaf(A2, q, B2);
        o = g2 ? wo : kt;
    }
}

// ---------------- launch ----------------
extern "C" void kernel_launch(void* const* d_in, const int* in_sizes, int n_in,
                              void* d_out, int out_size) {
    const float* x       = (const float*)d_in[0];
    const float* W_key   = (const float*)d_in[1];
    const float* W_value = (const float*)d_in[2];
    const float* W_recep = (const float*)d_in[3];
    const float* W_out   = (const float*)d_in[4];
    const float* decay   = (const float*)d_in[5];
    const float* first   = (const float*)d_in[6];
    float* out = (float*)d_out;

    float *k, *v, *sr;
    __nv_bfloat16 *ah, *al, *wh, *wl;
    cudaGetSymbolAddress((void**)&k,  g_k);
    cudaGetSymbolAddress((void**)&v,  g_v);
    cudaGetSymbolAddress((void**)&sr, g_sr);
    cudaGetSymbolAddress((void**)&ah, g_ah);
    cudaGetSymbolAddress((void**)&al, g_al);
    cudaGetSymbolAddress((void**)&wh, g_wh);
    cudaGetSymbolAddress((void**)&wl, g_wl);

    cudaFuncSetAttribute(gemm3_bf16, cudaFuncAttributeMaxDynamicSharedMemorySize, SM_TOT);
    cudaFuncSetAttribute(gemm1_bf16, cudaFuncAttributeMaxDynamicSharedMemorySize, SM_TOT);

    dim3 eb(256), eg(BTC / 4 / 256);
    dim3 cg(4 * CC * CC / 256);
    dim3 gb(256), gg3(12, GM / 128), gg1(4, GM / 128);
    dim3 wb(1024), wg(BB * (CC / CPB));   // 256 blocks

    shift_zigzag_bf16<<<eg, eb>>>(x, ah, al);
    conv_w4<<<cg, eb>>>(W_key, W_value, W_recep, W_out, wh, wl);
    gemm3_bf16<<<gg3, gb, SM_TOT>>>(ah, al, wh, wl, k, v, sr);
    wkv1<<<wg, wb>>>(decay, first, k, v, v);
    wkv2<<<wg, wb>>>(decay, first, k, v, sr, ah, al);
    gemm1_bf16<<<gg1, gb, SM_TOT>>>(ah, al, wh + 3 * (size_t)CC * CC, wl + 3 * (size_t)CC * CC, out);
}

// round 7
// speedup vs baseline: 10.3265x; 1.3189x over previous
#include <cuda_runtime.h>
#include <cuda_fp16.h>
#include <math.h>
#include <stdint.h>

// Fixed problem shape: B=8, H=W=64 -> T=4096, C=512
#define BB   8
#define TT   4096
#define CC   512
#define BTC  (BB*TT*CC)
#define GM   32768
#define GK   512

// ---------------- scratch ----------------
__device__ float  g_k [BTC];
__device__ float  g_v [BTC];          // v -> y1 in place
__device__ float  g_sr[BTC];
__device__ __half g_a [BTC];          // GEMM A (xi, then sr*y2), fp16
__device__ __half g_wh[4*CC*CC];      // weight hi
__device__ __half g_wl[4*CC*CC];      // weight lo

// ---------------- asm helpers ----------------
__device__ __forceinline__ uint32_t smem_u32(const void* p) {
    uint32_t a;
    asm("{ .reg .u64 t; cvta.to.shared.u64 t, %1; cvt.u32.u64 %0, t; }" : "=r"(a) : "l"(p));
    return a;
}
__device__ __forceinline__ void cp16(uint32_t d, const void* s) {
    asm volatile("cp.async.cg.shared.global [%0], [%1], 16;" :: "r"(d), "l"(s));
}
#define CP_COMMIT() asm volatile("cp.async.commit_group;" ::: "memory")
#define CP_WAIT0()  asm volatile("cp.async.wait_group 0;" ::: "memory")
#define CP_WAIT1()  asm volatile("cp.async.wait_group 1;" ::: "memory")

__device__ __forceinline__ void ldsm4(uint32_t* r, uint32_t a) {
    asm volatile("ldmatrix.sync.aligned.m8n8.x4.shared.b16 {%0,%1,%2,%3}, [%4];"
        : "=r"(r[0]), "=r"(r[1]), "=r"(r[2]), "=r"(r[3]) : "r"(a));
}
__device__ __forceinline__ void mma16816(float* c, const uint32_t* a, const uint32_t* b) {
    asm volatile("mma.sync.aligned.m16n8k16.row.col.f32.f16.f16.f32 "
        "{%0,%1,%2,%3}, {%4,%5,%6,%7}, {%8,%9}, {%0,%1,%2,%3};"
        : "+f"(c[0]), "+f"(c[1]), "+f"(c[2]), "+f"(c[3])
        : "r"(a[0]), "r"(a[1]), "r"(a[2]), "r"(a[3]), "r"(b[0]), "r"(b[1]));
}
#define SW64(o) ((o) ^ (((o) >> 3) & 0x30))

// ---------------- kernel 1: q_shift + zigzag -> fp16 ----------------
__global__ void shift_zigzag_f16(const float* __restrict__ x, __half* __restrict__ a) {
    int gid = blockIdx.x * 256 + threadIdx.x;       // float4 units
    int c4 = gid & 127;
    int tp = (gid >> 7) & (TT - 1);
    int b  = gid >> 19;
    int i  = tp >> 6;
    int jj = tp & 63;
    int col = (i & 1) ? (63 - jj) : jj;
    int grp = c4 >> 5;
    int hs = i, ws = col;
    bool valid;
    if (grp == 0)      { ws = col - 1; valid = (col >= 1);  }
    else if (grp == 1) { ws = col + 1; valid = (col <= 62); }
    else if (grp == 2) { hs = i - 1;   valid = (i >= 1);    }
    else               { hs = i + 1;   valid = (i <= 62);   }
    float4 v = make_float4(0.f, 0.f, 0.f, 0.f);
    if (valid)
        v = *(const float4*)(x + ((size_t)((b << 12) + (hs << 6) + ws) << 9) + (c4 << 2));
    __half h[4] = {__float2half_rn(v.x), __float2half_rn(v.y),
                   __float2half_rn(v.z), __float2half_rn(v.w)};
    *(uint2*)(a + ((size_t)gid << 2)) = *(uint2*)h;
}

// ---------------- kernel 2: weight fp16 hi/lo split ----------------
__global__ void conv_w4(const float* __restrict__ w0, const float* __restrict__ w1,
                        const float* __restrict__ w2, const float* __restrict__ w3,
                        __half* __restrict__ wh, __half* __restrict__ wl) {
    int gid = blockIdx.x * 256 + threadIdx.x;
    int sel = gid >> 18;
    int off = gid & (CC * CC - 1);
    const float* src = (sel == 0) ? w0 : (sel == 1) ? w1 : (sel == 2) ? w2 : w3;
    float v = src[off];
    __half h = __float2half_rn(v);
    wh[gid] = h;
    wl[gid] = __float2half_rn(v - __half2float(h));
}

// ---------------- GEMM: fp16 2-mma split, 128x128 tiles, 3-stage pipe ------
#define TILE_B (128 * 64)          // 8 KB per operand tile (128 rows x 32 halfs)
#define STG_B  (3 * TILE_B)        // A, Wh, Wl = 24 KB
#define SM_TOT (3 * STG_B)         // 72 KB

__device__ __forceinline__ void gemm_core(const __half* __restrict__ A,
                                          const __half* __restrict__ Wh,
                                          const __half* __restrict__ Wl,
                                          float* __restrict__ Co,
                                          int m0, int n0, bool sigm, char* smem) {
    const int tid = threadIdx.x;
    const int wid = tid >> 5;
    const int lane = tid & 31;
    const int wm = (wid & 3) * 32;
    const int wn = (wid >> 2) * 64;
    const uint32_t sb0 = smem_u32(smem);

    float acc[2][8][4];
    #pragma unroll
    for (int i = 0; i < 2; i++)
        #pragma unroll
        for (int j = 0; j < 8; j++)
            #pragma unroll
            for (int q = 0; q < 4; q++) acc[i][j][q] = 0.f;

    auto load_stage = [&](int kc, int s) {
        uint32_t sb = sb0 + s * STG_B;
        #pragma unroll
        for (int i = 0; i < 2; i++) {
            int idx = tid + i * 256;
            int r = idx >> 2, c16 = idx & 3;
            uint32_t sw = SW64((uint32_t)(r * 64 + c16 * 16));
            size_t ga = (size_t)(m0 + r) * GK + kc * 32 + c16 * 8;
            size_t gb = (size_t)(n0 + r) * GK + kc * 32 + c16 * 8;
            cp16(sb + sw,              A  + ga);
            cp16(sb + TILE_B + sw,     Wh + gb);
            cp16(sb + 2 * TILE_B + sw, Wl + gb);
        }
    };

    const int sub = lane >> 3, lrow = lane & 7;

    load_stage(0, 0); CP_COMMIT();
    load_stage(1, 1); CP_COMMIT();

    #pragma unroll 1
    for (int kc = 0; kc < 16; kc++) {
        if (kc < 14) { CP_WAIT1(); } else { CP_WAIT0(); }
        __syncthreads();
        if (kc + 2 < 16) {
            int s2 = (kc + 2) % 3;
            load_stage(kc + 2, s2); CP_COMMIT();
        }
        const uint32_t sb = sb0 + (kc % 3) * STG_B;

        #pragma unroll
        for (int k16 = 0; k16 < 2; k16++) {
            const uint32_t kbyte = (uint32_t)(k16 * 32 + (sub >> 1) * 16);
            uint32_t av[2][4], bh[8][2], bl[8][2];
            #pragma unroll
            for (int mt = 0; mt < 2; mt++) {
                int row = wm + mt * 16 + (sub & 1) * 8 + lrow;
                uint32_t so = SW64((uint32_t)(row * 64) + kbyte);
                ldsm4(av[mt], sb + so);
            }
            #pragma unroll
            for (int nt = 0; nt < 4; nt++) {
                int row = wn + nt * 16 + (sub & 1) * 8 + lrow;
                uint32_t so = SW64((uint32_t)(row * 64) + kbyte);
                uint32_t t0[4], t1[4];
                ldsm4(t0, sb + TILE_B + so);
                ldsm4(t1, sb + 2 * TILE_B + so);
                bh[2*nt][0] = t0[0]; bh[2*nt+1][0] = t0[1];
                bh[2*nt][1] = t0[2]; bh[2*nt+1][1] = t0[3];
                bl[2*nt][0] = t1[0]; bl[2*nt+1][0] = t1[1];
                bl[2*nt][1] = t1[2]; bl[2*nt+1][1] = t1[3];
            }
            #pragma unroll
            for (int mt = 0; mt < 2; mt++)
                #pragma unroll
                for (int n8 = 0; n8 < 8; n8++) {
                    mma16816(acc[mt][n8], av[mt], bh[n8]);
                    mma16816(acc[mt][n8], av[mt], bl[n8]);
                }
        }
    }

    const int g = lane >> 2, t = lane & 3;
    #pragma unroll
    for (int mt = 0; mt < 2; mt++) {
        #pragma unroll
        for (int n8 = 0; n8 < 8; n8++) {
            int row0 = m0 + wm + mt * 16 + g;
            int col  = n0 + wn + n8 * 8 + t * 2;
            float c0 = acc[mt][n8][0], c1 = acc[mt][n8][1];
            float c2 = acc[mt][n8][2], c3 = acc[mt][n8][3];
            if (sigm) {
                c0 = 1.f / (1.f + __expf(-c0));
                c1 = 1.f / (1.f + __expf(-c1));
                c2 = 1.f / (1.f + __expf(-c2));
                c3 = 1.f / (1.f + __expf(-c3));
            }
            *(float2*)(Co + (size_t)row0 * CC + col)       = make_float2(c0, c1);
            *(float2*)(Co + (size_t)(row0 + 8) * CC + col) = make_float2(c2, c3);
        }
    }
}

__global__ __launch_bounds__(256) void gemm3_f16(const __half* __restrict__ A,
                                                 const __half* __restrict__ Wh,
                                                 const __half* __restrict__ Wl,
                                                 float* __restrict__ Ko,
                                                 float* __restrict__ Vo,
                                                 float* __restrict__ So) {
    extern __shared__ char smem[];
    const int which = blockIdx.x >> 2;
    const int n0 = (blockIdx.x & 3) * 128;
    const int m0 = blockIdx.y * 128;
    float* Co = (which == 0) ? Ko : (which == 1) ? Vo : So;
    gemm_core(A, Wh + (size_t)which * CC * CC, Wl + (size_t)which * CC * CC,
              Co, m0, n0, which == 2, smem);
}

__global__ __launch_bounds__(256) void gemm1_f16(const __half* __restrict__ A,
                                                 const __half* __restrict__ Wh,
                                                 const __half* __restrict__ Wl,
                                                 float* __restrict__ Co) {
    extern __shared__ char smem[];
    gemm_core(A, Wh, Wl, Co, blockIdx.y * 128, blockIdx.x * 128, false, smem);
}

// ---------------- WKV scans (1-exp combine) ----------------
#define NCHUNK 64
#define CHL    (TT / NCHUNK)   // 64
#define CPB    16

__global__ __launch_bounds__(1024) void wkv1(const float* __restrict__ decay,
                                             const float* __restrict__ first,
                                             const float* __restrict__ K,
                                             const float* __restrict__ V,
                                             float* __restrict__ Y) {
    __shared__ float sp[NCHUNK][CPB + 1];
    __shared__ float sq[NCHUNK][CPB + 1];
    __shared__ float so[NCHUNK][CPB + 1];
    const int tid = threadIdx.x;
    const int cl = tid & (CPB - 1);
    const int ch = tid / CPB;
    const int cg = blockIdx.x & 31;
    const int b  = blockIdx.x >> 5;
    const int c  = cg * CPB + cl;
    const float inv_t = 1.0f / (float)TT;
    const float w = decay[c] * inv_t;
    const float u = first[c] * inv_t;
    const size_t base = ((size_t)(b * TT + ch * CHL)) * CC + c;

    float p = 0.f, q = 0.f, o = -1e38f;
    #pragma unroll 4
    for (int s = 0; s < CHL; s++) {
        float kt = K[base + (size_t)s * CC];
        float vt = V[base + (size_t)s * CC];
        float wo = w + o;
        float d  = wo - kt;
        float e  = __expf(-fabsf(d));
        bool ge  = (d >= 0.f);
        float A  = ge ? 1.f : e;
        float Bv = ge ? e : 1.f;
        p = fmaf(A, p, Bv * vt);
        q = fmaf(A, q, Bv);
        o = ge ? wo : kt;
    }
    sp[ch][cl] = p; sq[ch][cl] = q; so[ch][cl] = o;
    __syncthreads();

    if (ch == 0) {
        const float Lw = (float)CHL * w;
        float ap = 0.f, aq = 0.f, ao = -1e38f;
        #pragma unroll
        for (int i = 0; i < NCHUNK; i++) {
            float tp = sp[i][cl], tq = sq[i][cl], to = so[i][cl];
            sp[i][cl] = ap; sq[i][cl] = aq; so[i][cl] = ao;
            float od = ao + Lw;
            float d  = od - to;
            float e  = __expf(-fabsf(d));
            bool ge  = (d >= 0.f);
            float e1 = ge ? 1.f : e;
            float e2 = ge ? e : 1.f;
            ap = fmaf(e1, ap, e2 * tp);
            aq = fmaf(e1, aq, e2 * tq);
            ao = ge ? od : to;
        }
    }
    __syncthreads();
    p = sp[ch][cl]; q = sq[ch][cl]; o = so[ch][cl];

    #pragma unroll 4
    for (int s = 0; s < CHL; s++) {
        size_t idx = base + (size_t)s * CC;
        float kt = K[idx];
        float vt = V[idx];
        float uk = u + kt;
        float d1 = o - uk;
        float e1 = __expf(-fabsf(d1));
        bool g1  = (d1 >= 0.f);
        float A1 = g1 ? 1.f : e1;
        float B1 = g1 ? e1 : 1.f;
        Y[idx] = fmaf(A1, p, B1 * vt) / fmaf(A1, q, B1);
        float wo = w + o;
        float d2 = wo - kt;
        float e2 = __expf(-fabsf(d2));
        bool g2  = (d2 >= 0.f);
        float A2 = g2 ? 1.f : e2;
        float B2 = g2 ? e2 : 1.f;
        p = fmaf(A2, p, B2 * vt);
        q = fmaf(A2, q, B2);
        o = g2 ? wo : kt;
    }
}

// scan 2: zigzag-gathered reads (fused permute); epilogue writes fp16 sr*y.
__global__ __launch_bounds__(1024) void wkv2(const float* __restrict__ decay,
                                             const float* __restrict__ first,
                                             const float* __restrict__ K,
                                             const float* __restrict__ V,
                                             const float* __restrict__ SR,
                                             __half* __restrict__ Ao) {
    __shared__ float sp[NCHUNK][CPB + 1];
    __shared__ float sq[NCHUNK][CPB + 1];
    __shared__ float so[NCHUNK][CPB + 1];
    const int tid = threadIdx.x;
    const int cl = tid & (CPB - 1);
    const int ch = tid / CPB;          // chunk == image row (CHL == 64 == W)
    const int cg = blockIdx.x & 31;
    const int b  = blockIdx.x >> 5;
    const int c  = cg * CPB + cl;
    const float inv_t = 1.0f / (float)TT;
    const float w = decay[CC + c] * inv_t;
    const float u = first[CC + c] * inv_t;
    const bool rev = (ch & 1);
    const size_t brow = ((size_t)(b << 12) + (ch << 6));

    float p = 0.f, q = 0.f, o = -1e38f;
    #pragma unroll 4
    for (int s = 0; s < CHL; s++) {
        int col = rev ? (63 - s) : s;
        size_t idx = (brow + col) * CC + c;
        float kt = K[idx];
        float vt = V[idx];
        float wo = w + o;
        float d  = wo - kt;
        float e  = __expf(-fabsf(d));
        bool ge  = (d >= 0.f);
        float A  = ge ? 1.f : e;
        float Bv = ge ? e : 1.f;
        p = fmaf(A, p, Bv * vt);
        q = fmaf(A, q, Bv);
        o = ge ? wo : kt;
    }
    sp[ch][cl] = p; sq[ch][cl] = q; so[ch][cl] = o;
    __syncthreads();

    if (ch == 0) {
        const float Lw = (float)CHL * w;
        float ap = 0.f, aq = 0.f, ao = -1e38f;
        #pragma unroll
        for (int i = 0; i < NCHUNK; i++) {
            float tp = sp[i][cl], tq = sq[i][cl], to = so[i][cl];
            sp[i][cl] = ap; sq[i][cl] = aq; so[i][cl] = ao;
            float od = ao + Lw;
            float d  = od - to;
            float e  = __expf(-fabsf(d));
            bool ge  = (d >= 0.f);
            float e1 = ge ? 1.f : e;
            float e2 = ge ? e : 1.f;
            ap = fmaf(e1, ap, e2 * tp);
            aq = fmaf(e1, aq, e2 * tq);
            ao = ge ? od : to;
        }
    }
    __syncthreads();
    p = sp[ch][cl]; q = sq[ch][cl]; o = so[ch][cl];

    #pragma unroll 4
    for (int s = 0; s < CHL; s++) {
        int col = rev ? (63 - s) : s;
        size_t idx = (brow + col) * CC + c;
        size_t odx = ((size_t)(b * TT + ch * CHL + s)) * CC + c;
        float kt = K[idx];
        float vt = V[idx];
        float uk = u + kt;
        float d1 = o - uk;
        float e1 = __expf(-fabsf(d1));
        bool g1  = (d1 >= 0.f);
        float A1 = g1 ? 1.f : e1;
        float B1 = g1 ? e1 : 1.f;
        float y  = fmaf(A1, p, B1 * vt) / fmaf(A1, q, B1);
        Ao[odx] = __float2half_rn(SR[odx] * y);
        float wo = w + o;
        float d2 = wo - kt;
        float e2 = __expf(-fabsf(d2));
        bool g2  = (d2 >= 0.f);
        float A2 = g2 ? 1.f : e2;
        float B2 = g2 ? e2 : 1.f;
        p = fmaf(A2, p, B2 * vt);
        q = fmaf(A2, q, B2);
        o = g2 ? wo : kt;
    }
}

// ---------------- launch ----------------
extern "C" void kernel_launch(void* const* d_in, const int* in_sizes, int n_in,
                              void* d_out, int out_size) {
    const float* x       = (const float*)d_in[0];
    const float* W_key   = (const float*)d_in[1];
    const float* W_value = (const float*)d_in[2];
    const float* W_recep = (const float*)d_in[3];
    const float* W_out   = (const float*)d_in[4];
    const float* decay   = (const float*)d_in[5];
    const float* first   = (const float*)d_in[6];
    float* out = (float*)d_out;

    float *k, *v, *sr;
    __half *a, *wh, *wl;
    cudaGetSymbolAddress((void**)&k,  g_k);
    cudaGetSymbolAddress((void**)&v,  g_v);
    cudaGetSymbolAddress((void**)&sr, g_sr);
    cudaGetSymbolAddress((void**)&a,  g_a);
    cudaGetSymbolAddress((void**)&wh, g_wh);
    cudaGetSymbolAddress((void**)&wl, g_wl);

    cudaFuncSetAttribute(gemm3_f16, cudaFuncAttributeMaxDynamicSharedMemorySize, SM_TOT);
    cudaFuncSetAttribute(gemm1_f16, cudaFuncAttributeMaxDynamicSharedMemorySize, SM_TOT);

    dim3 eb(256), eg(BTC / 4 / 256);
    dim3 cg(4 * CC * CC / 256);
    dim3 gb(256), gg3(12, GM / 128), gg1(4, GM / 128);
    dim3 wb(1024), wg(BB * (CC / CPB));

    shift_zigzag_f16<<<eg, eb>>>(x, a);
    conv_w4<<<cg, eb>>>(W_key, W_value, W_recep, W_out, wh, wl);
    gemm3_f16<<<gg3, gb, SM_TOT>>>(a, wh, wl, k, v, sr);
    wkv1<<<wg, wb>>>(decay, first, k, v, v);
    wkv2<<<wg, wb>>>(decay, first, k, v, sr, a);
    gemm1_f16<<<gg1, gb, SM_TOT>>>(a, wh + 3 * (size_t)CC * CC, wl + 3 * (size_t)CC * CC, out);
}

// round 8
// speedup vs baseline: 13.4970x; 1.3070x over previous
#include <cuda_runtime.h>
#include <cuda_fp16.h>
#include <math.h>
#include <stdint.h>

// Fixed problem shape: B=8, H=W=64 -> T=4096, C=512
#define BB   8
#define TT   4096
#define CC   512
#define BTC  (BB*TT*CC)
#define GM   32768
#define GK   512

// ---------------- scratch ----------------
__device__ float  g_k [BTC];
__device__ float  g_v [BTC];          // v -> y1 in place
__device__ float  g_sr[BTC];
__device__ __half g_a [BTC];          // GEMM A (xi, then sr*y2), fp16
__device__ __half g_w [4*CC*CC];      // weights, fp16 (1-term)

// ---------------- asm helpers ----------------
__device__ __forceinline__ uint32_t smem_u32(const void* p) {
    uint32_t a;
    asm("{ .reg .u64 t; cvta.to.shared.u64 t, %1; cvt.u32.u64 %0, t; }" : "=r"(a) : "l"(p));
    return a;
}
__device__ __forceinline__ void cp16(uint32_t d, const void* s) {
    asm volatile("cp.async.cg.shared.global [%0], [%1], 16;" :: "r"(d), "l"(s));
}
#define CP_COMMIT() asm volatile("cp.async.commit_group;" ::: "memory")
#define CP_WAIT0()  asm volatile("cp.async.wait_group 0;" ::: "memory")
#define CP_WAIT1()  asm volatile("cp.async.wait_group 1;" ::: "memory")

__device__ __forceinline__ void ldsm4(uint32_t* r, uint32_t a) {
    asm volatile("ldmatrix.sync.aligned.m8n8.x4.shared.b16 {%0,%1,%2,%3}, [%4];"
        : "=r"(r[0]), "=r"(r[1]), "=r"(r[2]), "=r"(r[3]) : "r"(a));
}
__device__ __forceinline__ void mma16816(float* c, const uint32_t* a, const uint32_t* b) {
    asm volatile("mma.sync.aligned.m16n8k16.row.col.f32.f16.f16.f32 "
        "{%0,%1,%2,%3}, {%4,%5,%6,%7}, {%8,%9}, {%0,%1,%2,%3};"
        : "+f"(c[0]), "+f"(c[1]), "+f"(c[2]), "+f"(c[3])
        : "r"(a[0]), "r"(a[1]), "r"(a[2]), "r"(a[3]), "r"(b[0]), "r"(b[1]));
}
#define SW64(o) ((o) ^ (((o) >> 3) & 0x30))

// ---------------- kernel 1: q_shift + zigzag -> fp16 ----------------
__global__ void shift_zigzag_f16(const float* __restrict__ x, __half* __restrict__ a) {
    int gid = blockIdx.x * 256 + threadIdx.x;       // float4 units
    int c4 = gid & 127;
    int tp = (gid >> 7) & (TT - 1);
    int b  = gid >> 19;
    int i  = tp >> 6;
    int jj = tp & 63;
    int col = (i & 1) ? (63 - jj) : jj;
    int grp = c4 >> 5;
    int hs = i, ws = col;
    bool valid;
    if (grp == 0)      { ws = col - 1; valid = (col >= 1);  }
    else if (grp == 1) { ws = col + 1; valid = (col <= 62); }
    else if (grp == 2) { hs = i - 1;   valid = (i >= 1);    }
    else               { hs = i + 1;   valid = (i <= 62);   }
    float4 v = make_float4(0.f, 0.f, 0.f, 0.f);
    if (valid)
        v = *(const float4*)(x + ((size_t)((b << 12) + (hs << 6) + ws) << 9) + (c4 << 2));
    __half h[4] = {__float2half_rn(v.x), __float2half_rn(v.y),
                   __float2half_rn(v.z), __float2half_rn(v.w)};
    *(uint2*)(a + ((size_t)gid << 2)) = *(uint2*)h;
}

// ---------------- kernel 2: weight fp16 conversion ----------------
__global__ void conv_w4(const float* __restrict__ w0, const float* __restrict__ w1,
                        const float* __restrict__ w2, const float* __restrict__ w3,
                        __half* __restrict__ wo) {
    int gid = blockIdx.x * 256 + threadIdx.x;
    int sel = gid >> 18;
    int off = gid & (CC * CC - 1);
    const float* src = (sel == 0) ? w0 : (sel == 1) ? w1 : (sel == 2) ? w2 : w3;
    wo[gid] = __float2half_rn(src[off]);
}

// ---------------- GEMM: fp16 1-mma, 128x128 tiles, 3-stage pipe ------
#define TILE_B (128 * 64)          // 8 KB per operand tile (128 rows x 32 halfs)
#define STG_B  (2 * TILE_B)        // A, W = 16 KB
#define SM_TOT (3 * STG_B)         // 48 KB

__device__ __forceinline__ void gemm_core(const __half* __restrict__ A,
                                          const __half* __restrict__ W,
                                          float* __restrict__ Co,
                                          int m0, int n0, bool sigm, char* smem) {
    const int tid = threadIdx.x;
    const int wid = tid >> 5;
    const int lane = tid & 31;
    const int wm = (wid & 3) * 32;
    const int wn = (wid >> 2) * 64;
    const uint32_t sb0 = smem_u32(smem);

    float acc[2][8][4];
    #pragma unroll
    for (int i = 0; i < 2; i++)
        #pragma unroll
        for (int j = 0; j < 8; j++)
            #pragma unroll
            for (int q = 0; q < 4; q++) acc[i][j][q] = 0.f;

    auto load_stage = [&](int kc, int s) {
        uint32_t sb = sb0 + s * STG_B;
        #pragma unroll
        for (int i = 0; i < 2; i++) {
            int idx = tid + i * 256;
            int r = idx >> 2, c16 = idx & 3;
            uint32_t sw = SW64((uint32_t)(r * 64 + c16 * 16));
            size_t ga = (size_t)(m0 + r) * GK + kc * 32 + c16 * 8;
            size_t gb = (size_t)(n0 + r) * GK + kc * 32 + c16 * 8;
            cp16(sb + sw,          A + ga);
            cp16(sb + TILE_B + sw, W + gb);
        }
    };

    const int sub = lane >> 3, lrow = lane & 7;

    load_stage(0, 0); CP_COMMIT();
    load_stage(1, 1); CP_COMMIT();

    #pragma unroll 1
    for (int kc = 0; kc < 16; kc++) {
        if (kc < 14) { CP_WAIT1(); } else { CP_WAIT0(); }
        __syncthreads();
        if (kc + 2 < 16) {
            int s2 = (kc + 2) % 3;
            load_stage(kc + 2, s2); CP_COMMIT();
        }
        const uint32_t sb = sb0 + (kc % 3) * STG_B;

        #pragma unroll
        for (int k16 = 0; k16 < 2; k16++) {
            const uint32_t kbyte = (uint32_t)(k16 * 32 + (sub >> 1) * 16);
            uint32_t av[2][4], bh[8][2];
            #pragma unroll
            for (int mt = 0; mt < 2; mt++) {
                int row = wm + mt * 16 + (sub & 1) * 8 + lrow;
                uint32_t so = SW64((uint32_t)(row * 64) + kbyte);
                ldsm4(av[mt], sb + so);
            }
            #pragma unroll
            for (int nt = 0; nt < 4; nt++) {
                int row = wn + nt * 16 + (sub & 1) * 8 + lrow;
                uint32_t so = SW64((uint32_t)(row * 64) + kbyte);
                uint32_t t0[4];
                ldsm4(t0, sb + TILE_B + so);
                bh[2*nt][0] = t0[0]; bh[2*nt+1][0] = t0[1];
                bh[2*nt][1] = t0[2]; bh[2*nt+1][1] = t0[3];
            }
            #pragma unroll
            for (int mt = 0; mt < 2; mt++)
                #pragma unroll
                for (int n8 = 0; n8 < 8; n8++)
                    mma16816(acc[mt][n8], av[mt], bh[n8]);
        }
    }

    const int g = lane >> 2, t = lane & 3;
    #pragma unroll
    for (int mt = 0; mt < 2; mt++) {
        #pragma unroll
        for (int n8 = 0; n8 < 8; n8++) {
            int row0 = m0 + wm + mt * 16 + g;
            int col  = n0 + wn + n8 * 8 + t * 2;
            float c0 = acc[mt][n8][0], c1 = acc[mt][n8][1];
            float c2 = acc[mt][n8][2], c3 = acc[mt][n8][3];
            if (sigm) {
                c0 = 1.f / (1.f + __expf(-c0));
                c1 = 1.f / (1.f + __expf(-c1));
                c2 = 1.f / (1.f + __expf(-c2));
                c3 = 1.f / (1.f + __expf(-c3));
            }
            *(float2*)(Co + (size_t)row0 * CC + col)       = make_float2(c0, c1);
            *(float2*)(Co + (size_t)(row0 + 8) * CC + col) = make_float2(c2, c3);
        }
    }
}

__global__ __launch_bounds__(256) void gemm3_f16(const __half* __restrict__ A,
                                                 const __half* __restrict__ W,
                                                 float* __restrict__ Ko,
                                                 float* __restrict__ Vo,
                                                 float* __restrict__ So) {
    extern __shared__ char smem[];
    const int which = blockIdx.x >> 2;
    const int n0 = (blockIdx.x & 3) * 128;
    const int m0 = blockIdx.y * 128;
    float* Co = (which == 0) ? Ko : (which == 1) ? Vo : So;
    gemm_core(A, W + (size_t)which * CC * CC, Co, m0, n0, which == 2, smem);
}

__global__ __launch_bounds__(256) void gemm1_f16(const __half* __restrict__ A,
                                                 const __half* __restrict__ W,
                                                 float* __restrict__ Co) {
    extern __shared__ char smem[];
    gemm_core(A, W, Co, blockIdx.y * 128, blockIdx.x * 128, false, smem);
}

// ---------------- WKV scans (1-exp combine) ----------------
#define NCHUNK 64
#define CHL    (TT / NCHUNK)   // 64
#define CPB    16

__global__ __launch_bounds__(1024) void wkv1(const float* __restrict__ decay,
                                             const float* __restrict__ first,
                                             const float* __restrict__ K,
                                             const float* __restrict__ V,
                                             float* __restrict__ Y) {
    __shared__ float sp[NCHUNK][CPB + 1];
    __shared__ float sq[NCHUNK][CPB + 1];
    __shared__ float so[NCHUNK][CPB + 1];
    const int tid = threadIdx.x;
    const int cl = tid & (CPB - 1);
    const int ch = tid / CPB;
    const int cg = blockIdx.x & 31;
    const int b  = blockIdx.x >> 5;
    const int c  = cg * CPB + cl;
    const float inv_t = 1.0f / (float)TT;
    const float w = decay[c] * inv_t;
    const float u = first[c] * inv_t;
    const size_t base = ((size_t)(b * TT + ch * CHL)) * CC + c;

    float p = 0.f, q = 0.f, o = -1e38f;
    #pragma unroll 4
    for (int s = 0; s < CHL; s++) {
        float kt = K[base + (size_t)s * CC];
        float vt = V[base + (size_t)s * CC];
        float wo = w + o;
        float d  = wo - kt;
        float e  = __expf(-fabsf(d));
        bool ge  = (d >= 0.f);
        float A  = ge ? 1.f : e;
        float Bv = ge ? e : 1.f;
        p = fmaf(A, p, Bv * vt);
        q = fmaf(A, q, Bv);
        o = ge ? wo : kt;
    }
    sp[ch][cl] = p; sq[ch][cl] = q; so[ch][cl] = o;
    __syncthreads();

    if (ch == 0) {
        const float Lw = (float)CHL * w;
        float ap = 0.f, aq = 0.f, ao = -1e38f;
        #pragma unroll
        for (int i = 0; i < NCHUNK; i++) {
            float tp = sp[i][cl], tq = sq[i][cl], to = so[i][cl];
            sp[i][cl] = ap; sq[i][cl] = aq; so[i][cl] = ao;
            float od = ao + Lw;
            float d  = od - to;
            float e  = __expf(-fabsf(d));
            bool ge  = (d >= 0.f);
            float e1 = ge ? 1.f : e;
            float e2 = ge ? e : 1.f;
            ap = fmaf(e1, ap, e2 * tp);
            aq = fmaf(e1, aq, e2 * tq);
            ao = ge ? od : to;
        }
    }
    __syncthreads();
    p = sp[ch][cl]; q = sq[ch][cl]; o = so[ch][cl];

    #pragma unroll 4
    for (int s = 0; s < CHL; s++) {
        size_t idx = base + (size_t)s * CC;
        float kt = K[idx];
        float vt = V[idx];
        float uk = u + kt;
        float d1 = o - uk;
        float e1 = __expf(-fabsf(d1));
        bool g1  = (d1 >= 0.f);
        float A1 = g1 ? 1.f : e1;
        float B1 = g1 ? e1 : 1.f;
        Y[idx] = fmaf(A1, p, B1 * vt) / fmaf(A1, q, B1);
        float wo = w + o;
        float d2 = wo - kt;
        float e2 = __expf(-fabsf(d2));
        bool g2  = (d2 >= 0.f);
        float A2 = g2 ? 1.f : e2;
        float B2 = g2 ? e2 : 1.f;
        p = fmaf(A2, p, B2 * vt);
        q = fmaf(A2, q, B2);
        o = g2 ? wo : kt;
    }
}

// scan 2: zigzag-gathered reads (fused permute); epilogue writes fp16 sr*y.
__global__ __launch_bounds__(1024) void wkv2(const float* __restrict__ decay,
                                             const float* __restrict__ first,
                                             const float* __restrict__ K,
                                             const float* __restrict__ V,
                                             const float* __restrict__ SR,
                                             __half* __restrict__ Ao) {
    __shared__ float sp[NCHUNK][CPB + 1];
    __shared__ float sq[NCHUNK][CPB + 1];
    __shared__ float so[NCHUNK][CPB + 1];
    const int tid = threadIdx.x;
    const int cl = tid & (CPB - 1);
    const int ch = tid / CPB;          // chunk == image row (CHL == 64 == W)
    const int cg = blockIdx.x & 31;
    const int b  = blockIdx.x >> 5;
    const int c  = cg * CPB + cl;
    const float inv_t = 1.0f / (float)TT;
    const float w = decay[CC + c] * inv_t;
    const float u = first[CC + c] * inv_t;
    const bool rev = (ch & 1);
    const size_t brow = ((size_t)(b << 12) + (ch << 6));

    float p = 0.f, q = 0.f, o = -1e38f;
    #pragma unroll 4
    for (int s = 0; s < CHL; s++) {
        int col = rev ? (63 - s) : s;
        size_t idx = (brow + col) * CC + c;
        float kt = K[idx];
        float vt = V[idx];
        float wo = w + o;
        float d  = wo - kt;
        float e  = __expf(-fabsf(d));
        bool ge  = (d >= 0.f);
        float A  = ge ? 1.f : e;
        float Bv = ge ? e : 1.f;
        p = fmaf(A, p, Bv * vt);
        q = fmaf(A, q, Bv);
        o = ge ? wo : kt;
    }
    sp[ch][cl] = p; sq[ch][cl] = q; so[ch][cl] = o;
    __syncthreads();

    if (ch == 0) {
        const float Lw = (float)CHL * w;
        float ap = 0.f, aq = 0.f, ao = -1e38f;
        #pragma unroll
        for (int i = 0; i < NCHUNK; i++) {
            float tp = sp[i][cl], tq = sq[i][cl], to = so[i][cl];
            sp[i][cl] = ap; sq[i][cl] = aq; so[i][cl] = ao;
            float od = ao + Lw;
            float d  = od - to;
            float e  = __expf(-fabsf(d));
            bool ge  = (d >= 0.f);
            float e1 = ge ? 1.f : e;
            float e2 = ge ? e : 1.f;
            ap = fmaf(e1, ap, e2 * tp);
            aq = fmaf(e1, aq, e2 * tq);
            ao = ge ? od : to;
        }
    }
    __syncthreads();
    p = sp[ch][cl]; q = sq[ch][cl]; o = so[ch][cl];

    #pragma unroll 4
    for (int s = 0; s < CHL; s++) {
        int col = rev ? (63 - s) : s;
        size_t idx = (brow + col) * CC + c;
        size_t odx = ((size_t)(b * TT + ch * CHL + s)) * CC + c;
        float kt = K[idx];
        float vt = V[idx];
        float uk = u + kt;
        float d1 = o - uk;
        float e1 = __expf(-fabsf(d1));
        bool g1  = (d1 >= 0.f);
        float A1 = g1 ? 1.f : e1;
        float B1 = g1 ? e1 : 1.f;
        float y  = fmaf(A1, p, B1 * vt) / fmaf(A1, q, B1);
        Ao[odx] = __float2half_rn(SR[odx] * y);
        float wo = w + o;
        float d2 = wo - kt;
        float e2 = __expf(-fabsf(d2));
        bool g2  = (d2 >= 0.f);
        float A2 = g2 ? 1.f : e2;
        float B2 = g2 ? e2 : 1.f;
        p = fmaf(A2, p, B2 * vt);
        q = fmaf(A2, q, B2);
        o = g2 ? wo : kt;
    }
}

// ---------------- launch ----------------
extern "C" void kernel_launch(void* const* d_in, const int* in_sizes, int n_in,
                              void* d_out, int out_size) {
    const float* x       = (const float*)d_in[0];
    const float* W_key   = (const float*)d_in[1];
    const float* W_value = (const float*)d_in[2];
    const float* W_recep = (const float*)d_in[3];
    const float* W_out   = (const float*)d_in[4];
    const float* decay   = (const float*)d_in[5];
    const float* first   = (const float*)d_in[6];
    float* out = (float*)d_out;

    float *k, *v, *sr;
    __half *a, *w;
    cudaGetSymbolAddress((void**)&k,  g_k);
    cudaGetSymbolAddress((void**)&v,  g_v);
    cudaGetSymbolAddress((void**)&sr, g_sr);
    cudaGetSymbolAddress((void**)&a,  g_a);
    cudaGetSymbolAddress((void**)&w,  g_w);

    cudaFuncSetAttribute(gemm3_f16, cudaFuncAttributeMaxDynamicSharedMemorySize, SM_TOT);
    cudaFuncSetAttribute(gemm1_f16, cudaFuncAttributeMaxDynamicSharedMemorySize, SM_TOT);

    dim3 eb(256), eg(BTC / 4 / 256);
    dim3 cg(4 * CC * CC / 256);
    dim3 gb(256), gg3(12, GM / 128), gg1(4, GM / 128);
    dim3 wb(1024), wg(BB * (CC / CPB));

    shift_zigzag_f16<<<eg, eb>>>(x, a);
    conv_w4<<<cg, eb>>>(W_key, W_value, W_recep, W_out, w);
    gemm3_f16<<<gg3, gb, SM_TOT>>>(a, w, k, v, sr);
    wkv1<<<wg, wb>>>(decay, first, k, v, v);
    wkv2<<<wg, wb>>>(decay, first, k, v, sr, a);
    gemm1_f16<<<gg1, gb, SM_TOT>>>(a, w + 3 * (size_t)CC * CC, out);
}

// round 10
// speedup vs baseline: 14.4851x; 1.0732x over previous
#include <cuda_runtime.h>
#include <cuda_fp16.h>
#include <math.h>
#include <stdint.h>

// Fixed problem shape: B=8, H=W=64 -> T=4096, C=512
#define BB   8
#define TT   4096
#define CC   512
#define BTC  (BB*TT*CC)
#define GM   32768
#define GK   512

// ---------------- scratch ----------------
__device__ __half g_kh[BTC];          // k (fp16)
__device__ float  g_v [BTC];          // v -> y1 in place (fp32)
__device__ __half g_srh[BTC];         // sr (fp16)
__device__ __half g_a [BTC];          // GEMM A (xi, then sr*y2), fp16
__device__ __half g_w [4*CC*CC];      // weights, fp16

// ---------------- asm helpers ----------------
__device__ __forceinline__ uint32_t smem_u32(const void* p) {
    uint32_t a;
    asm("{ .reg .u64 t; cvta.to.shared.u64 t, %1; cvt.u32.u64 %0, t; }" : "=r"(a) : "l"(p));
    return a;
}
__device__ __forceinline__ void cp16(uint32_t d, const void* s) {
    asm volatile("cp.async.cg.shared.global [%0], [%1], 16;" :: "r"(d), "l"(s));
}
#define CP_COMMIT() asm volatile("cp.async.commit_group;" ::: "memory")
#define CP_WAIT0()  asm volatile("cp.async.wait_group 0;" ::: "memory")
#define CP_WAIT1()  asm volatile("cp.async.wait_group 1;" ::: "memory")

__device__ __forceinline__ void ldsm4(uint32_t* r, uint32_t a) {
    asm volatile("ldmatrix.sync.aligned.m8n8.x4.shared.b16 {%0,%1,%2,%3}, [%4];"
        : "=r"(r[0]), "=r"(r[1]), "=r"(r[2]), "=r"(r[3]) : "r"(a));
}
__device__ __forceinline__ void mma16816(float* c, const uint32_t* a, const uint32_t* b) {
    asm volatile("mma.sync.aligned.m16n8k16.row.col.f32.f16.f16.f32 "
        "{%0,%1,%2,%3}, {%4,%5,%6,%7}, {%8,%9}, {%0,%1,%2,%3};"
        : "+f"(c[0]), "+f"(c[1]), "+f"(c[2]), "+f"(c[3])
        : "r"(a[0]), "r"(a[1]), "r"(a[2]), "r"(a[3]), "r"(b[0]), "r"(b[1]));
}
#define SW64(o) ((o) ^ (((o) >> 3) & 0x30))

// ---------------- kernel 1: q_shift + zigzag -> fp16 ----------------
__global__ void shift_zigzag_f16(const float* __restrict__ x, __half* __restrict__ a) {
    int gid = blockIdx.x * 256 + threadIdx.x;       // float4 units
    int c4 = gid & 127;
    int tp = (gid >> 7) & (TT - 1);
    int b  = gid >> 19;
    int i  = tp >> 6;
    int jj = tp & 63;
    int col = (i & 1) ? (63 - jj) : jj;
    int grp = c4 >> 5;
    int hs = i, ws = col;
    bool valid;
    if (grp == 0)      { ws = col - 1; valid = (col >= 1);  }
    else if (grp == 1) { ws = col + 1; valid = (col <= 62); }
    else if (grp == 2) { hs = i - 1;   valid = (i >= 1);    }
    else               { hs = i + 1;   valid = (i <= 62);   }
    float4 v = make_float4(0.f, 0.f, 0.f, 0.f);
    if (valid)
        v = *(const float4*)(x + ((size_t)((b << 12) + (hs << 6) + ws) << 9) + (c4 << 2));
    __half h[4] = {__float2half_rn(v.x), __float2half_rn(v.y),
                   __float2half_rn(v.z), __float2half_rn(v.w)};
    *(uint2*)(a + ((size_t)gid << 2)) = *(uint2*)h;
}

// ---------------- kernel 2: weight fp16 conversion ----------------
__global__ void conv_w4(const float* __restrict__ w0, const float* __restrict__ w1,
                        const float* __restrict__ w2, const float* __restrict__ w3,
                        __half* __restrict__ wo) {
    int gid = blockIdx.x * 256 + threadIdx.x;
    int sel = gid >> 18;
    int off = gid & (CC * CC - 1);
    const float* src = (sel == 0) ? w0 : (sel == 1) ? w1 : (sel == 2) ? w2 : w3;
    wo[gid] = __float2half_rn(src[off]);
}

// ---------------- GEMM: fp16 1-mma, 128x128 tiles, 3-stage pipe ------
#define TILE_B (128 * 64)
#define STG_B  (2 * TILE_B)        // 16 KB
#define SM_TOT (3 * STG_B)         // 48 KB

__device__ __forceinline__ void gemm_core(const __half* __restrict__ A,
                                          const __half* __restrict__ W,
                                          float* __restrict__ Co,
                                          __half* __restrict__ HCo,
                                          int m0, int n0, bool sigm, bool half_out,
                                          char* smem) {
    const int tid = threadIdx.x;
    const int wid = tid >> 5;
    const int lane = tid & 31;
    const int wm = (wid & 3) * 32;
    const int wn = (wid >> 2) * 64;
    const uint32_t sb0 = smem_u32(smem);

    float acc[2][8][4];
    #pragma unroll
    for (int i = 0; i < 2; i++)
        #pragma unroll
        for (int j = 0; j < 8; j++)
            #pragma unroll
            for (int q = 0; q < 4; q++) acc[i][j][q] = 0.f;

    auto load_stage = [&](int kc, int s) {
        uint32_t sb = sb0 + s * STG_B;
        #pragma unroll
        for (int i = 0; i < 2; i++) {
            int idx = tid + i * 256;
            int r = idx >> 2, c16 = idx & 3;
            uint32_t sw = SW64((uint32_t)(r * 64 + c16 * 16));
            size_t ga = (size_t)(m0 + r) * GK + kc * 32 + c16 * 8;
            size_t gb = (size_t)(n0 + r) * GK + kc * 32 + c16 * 8;
            cp16(sb + sw,          A + ga);
            cp16(sb + TILE_B + sw, W + gb);
        }
    };

    const int sub = lane >> 3, lrow = lane & 7;

    load_stage(0, 0); CP_COMMIT();
    load_stage(1, 1); CP_COMMIT();

    #pragma unroll 1
    for (int kc = 0; kc < 16; kc++) {
        if (kc < 14) { CP_WAIT1(); } else { CP_WAIT0(); }
        __syncthreads();
        if (kc + 2 < 16) {
            int s2 = (kc + 2) % 3;
            load_stage(kc + 2, s2); CP_COMMIT();
        }
        const uint32_t sb = sb0 + (kc % 3) * STG_B;

        #pragma unroll
        for (int k16 = 0; k16 < 2; k16++) {
            const uint32_t kbyte = (uint32_t)(k16 * 32 + (sub >> 1) * 16);
            uint32_t av[2][4], bh[8][2];
            #pragma unroll
            for (int mt = 0; mt < 2; mt++) {
                int row = wm + mt * 16 + (sub & 1) * 8 + lrow;
                uint32_t so = SW64((uint32_t)(row * 64) + kbyte);
                ldsm4(av[mt], sb + so);
            }
            #pragma unroll
            for (int nt = 0; nt < 4; nt++) {
                int row = wn + nt * 16 + (sub & 1) * 8 + lrow;
                uint32_t so = SW64((uint32_t)(row * 64) + kbyte);
                uint32_t t0[4];
                ldsm4(t0, sb + TILE_B + so);
                bh[2*nt][0] = t0[0]; bh[2*nt+1][0] = t0[1];
                bh[2*nt][1] = t0[2]; bh[2*nt+1][1] = t0[3];
            }
            #pragma unroll
            for (int mt = 0; mt < 2; mt++)
                #pragma unroll
                for (int n8 = 0; n8 < 8; n8++)
                    mma16816(acc[mt][n8], av[mt], bh[n8]);
        }
    }

    const int g = lane >> 2, t = lane & 3;
    #pragma unroll
    for (int mt = 0; mt < 2; mt++) {
        #pragma unroll
        for (int n8 = 0; n8 < 8; n8++) {
            int row0 = m0 + wm + mt * 16 + g;
            int col  = n0 + wn + n8 * 8 + t * 2;
            float c0 = acc[mt][n8][0], c1 = acc[mt][n8][1];
            float c2 = acc[mt][n8][2], c3 = acc[mt][n8][3];
            if (sigm) {
                c0 = 1.f / (1.f + __expf(-c0));
                c1 = 1.f / (1.f + __expf(-c1));
                c2 = 1.f / (1.f + __expf(-c2));
                c3 = 1.f / (1.f + __expf(-c3));
            }
            if (half_out) {
                *(__half2*)(HCo + (size_t)row0 * CC + col)       = __floats2half2_rn(c0, c1);
                *(__half2*)(HCo + (size_t)(row0 + 8) * CC + col) = __floats2half2_rn(c2, c3);
            } else {
                *(float2*)(Co + (size_t)row0 * CC + col)       = make_float2(c0, c1);
                *(float2*)(Co + (size_t)(row0 + 8) * CC + col) = make_float2(c2, c3);
            }
        }
    }
}

// fused k|v|sr: k and sr emitted fp16, v fp32
__global__ __launch_bounds__(256) void gemm3_f16(const __half* __restrict__ A,
                                                 const __half* __restrict__ W,
                                                 __half* __restrict__ Kh,
                                                 float* __restrict__ Vo,
                                                 __half* __restrict__ Sh) {
    extern __shared__ char smem[];
    const int which = blockIdx.x >> 2;
    const int n0 = (blockIdx.x & 3) * 128;
    const int m0 = blockIdx.y * 128;
    float* Co = (which == 1) ? Vo : nullptr;
    __half* HCo = (which == 0) ? Kh : Sh;
    gemm_core(A, W + (size_t)which * CC * CC, Co, HCo, m0, n0,
              which == 2, which != 1, smem);
}

__global__ __launch_bounds__(256) void gemm1_f16(const __half* __restrict__ A,
                                                 const __half* __restrict__ W,
                                                 float* __restrict__ Co) {
    extern __shared__ char smem[];
    gemm_core(A, W, Co, nullptr, blockIdx.y * 128, blockIdx.x * 128, false, false, smem);
}

// ---------------- WKV scans (1-exp combine, fp16 k/sr) ----------------
#define NCHUNK 64
#define CHL    (TT / NCHUNK)   // 64
#define CPB    16

__global__ __launch_bounds__(1024) void wkv1(const float* __restrict__ decay,
                                             const float* __restrict__ first,
                                             const __half* __restrict__ K,
                                             const float* __restrict__ V,
                                             float* __restrict__ Y) {
    __shared__ float sp[NCHUNK][CPB + 1];
    __shared__ float sq[NCHUNK][CPB + 1];
    __shared__ float so[NCHUNK][CPB + 1];
    const int tid = threadIdx.x;
    const int cl = tid & (CPB - 1);
    const int ch = tid / CPB;
    const int cg = blockIdx.x & 31;
    const int b  = blockIdx.x >> 5;
    const int c  = cg * CPB + cl;
    const float inv_t = 1.0f / (float)TT;
    const float w = decay[c] * inv_t;
    const float u = first[c] * inv_t;
    const size_t base = ((size_t)(b * TT + ch * CHL)) * CC + c;

    float p = 0.f, q = 0.f, o = -1e38f;
    #pragma unroll 8
    for (int s = 0; s < CHL; s++) {
        float kt = __half2float(K[base + (size_t)s * CC]);
        float vt = V[base + (size_t)s * CC];
        float wo = w + o;
        float d  = wo - kt;
        float e  = __expf(-fabsf(d));
        bool ge  = (d >= 0.f);
        float A  = ge ? 1.f : e;
        float Bv = ge ? e : 1.f;
        p = fmaf(A, p, Bv * vt);
        q = fmaf(A, q, Bv);
        o = ge ? wo : kt;
    }
    sp[ch][cl] = p; sq[ch][cl] = q; so[ch][cl] = o;
    __syncthreads();

    if (ch == 0) {
        const float Lw = (float)CHL * w;
        float ap = 0.f, aq = 0.f, ao = -1e38f;
        #pragma unroll
        for (int i = 0; i < NCHUNK; i++) {
            float tp = sp[i][cl], tq = sq[i][cl], to = so[i][cl];
            sp[i][cl] = ap; sq[i][cl] = aq; so[i][cl] = ao;
            float od = ao + Lw;
            float d  = od - to;
            float e  = __expf(-fabsf(d));
            bool ge  = (d >= 0.f);
            float e1 = ge ? 1.f : e;
            float e2 = ge ? e : 1.f;
            ap = fmaf(e1, ap, e2 * tp);
            aq = fmaf(e1, aq, e2 * tq);
            ao = ge ? od : to;
        }
    }
    __syncthreads();
    p = sp[ch][cl]; q = sq[ch][cl]; o = so[ch][cl];

    #pragma unroll 8
    for (int s = 0; s < CHL; s++) {
        size_t idx = base + (size_t)s * CC;
        float kt = __half2float(K[idx]);
        float vt = V[idx];
        float uk = u + kt;
        float d1 = o - uk;
        float e1 = __expf(-fabsf(d1));
        bool g1  = (d1 >= 0.f);
        float A1 = g1 ? 1.f : e1;
        float B1 = g1 ? e1 : 1.f;
        Y[idx] = fmaf(A1, p, B1 * vt) / fmaf(A1, q, B1);
        float wo = w + o;
        float d2 = wo - kt;
        float e2 = __expf(-fabsf(d2));
        bool g2  = (d2 >= 0.f);
        float A2 = g2 ? 1.f : e2;
        float B2 = g2 ? e2 : 1.f;
        p = fmaf(A2, p, B2 * vt);
        q = fmaf(A2, q, B2);
        o = g2 ? wo : kt;
    }
}

// scan 2: zigzag-gathered reads (fused permute); epilogue writes fp16 sr*y.
__global__ __launch_bounds__(1024) void wkv2(const float* __restrict__ decay,
                                             const float* __restrict__ first,
                                             const __half* __restrict__ K,
                                             const float* __restrict__ V,
                                             const __half* __restrict__ SR,
                                             __half* __restrict__ Ao) {
    __shared__ float sp[NCHUNK][CPB + 1];
    __shared__ float sq[NCHUNK][CPB + 1];
    __shared__ float so[NCHUNK][CPB + 1];
    const int tid = threadIdx.x;
    const int cl = tid & (CPB - 1);
    const int ch = tid / CPB;          // chunk == image row (CHL == 64 == W)
    const int cg = blockIdx.x & 31;
    const int b  = blockIdx.x >> 5;
    const int c  = cg * CPB + cl;
    const float inv_t = 1.0f / (float)TT;
    const float w = decay[CC + c] * inv_t;
    const float u = first[CC + c] * inv_t;
    const bool rev = (ch & 1);
    const size_t brow = ((size_t)(b << 12) + (ch << 6));

    float p = 0.f, q = 0.f, o = -1e38f;
    #pragma unroll 8
    for (int s = 0; s < CHL; s++) {
        int col = rev ? (63 - s) : s;
        size_t idx = (brow + col) * CC + c;
        float kt = __half2float(K[idx]);
        float vt = V[idx];
        float wo = w + o;
        float d  = wo - kt;
        float e  = __expf(-fabsf(d));
        bool ge  = (d >= 0.f);
        float A  = ge ? 1.f : e;
        float Bv = ge ? e : 1.f;
        p = fmaf(A, p, Bv * vt);
        q = fmaf(A, q, Bv);
        o = ge ? wo : kt;
    }
    sp[ch][cl] = p; sq[ch][cl] = q; so[ch][cl] = o;
    __syncthreads();

    if (ch == 0) {
        const float Lw = (float)CHL * w;
        float ap = 0.f, aq = 0.f, ao = -1e38f;
        #pragma unroll
        for (int i = 0; i < NCHUNK; i++) {
            float tp = sp[i][cl], tq = sq[i][cl], to = so[i][cl];
            sp[i][cl] = ap; sq[i][cl] = aq; so[i][cl] = ao;
            float od = ao + Lw;
            float d  = od - to;
            float e  = __expf(-fabsf(d));
            bool ge  = (d >= 0.f);
            float e1 = ge ? 1.f : e;
            float e2 = ge ? e : 1.f;
            ap = fmaf(e1, ap, e2 * tp);
            aq = fmaf(e1, aq, e2 * tq);
            ao = ge ? od : to;
        }
    }
    __syncthreads();
    p = sp[ch][cl]; q = sq[ch][cl]; o = so[ch][cl];

    #pragma unroll 8
    for (int s = 0; s < CHL; s++) {
        int col = rev ? (63 - s) : s;
        size_t idx = (brow + col) * CC + c;
        size_t odx = ((size_t)(b * TT + ch * CHL + s)) * CC + c;
        float kt = __half2float(K[idx]);
        float vt = V[idx];
        float uk = u + kt;
        float d1 = o - uk;
        float e1 = __expf(-fabsf(d1));
        bool g1  = (d1 >= 0.f);
        float A1 = g1 ? 1.f : e1;
        float B1 = g1 ? e1 : 1.f;
        float y  = fmaf(A1, p, B1 * vt) / fmaf(A1, q, B1);
        Ao[odx] = __float2half_rn(__half2float(SR[odx]) * y);
        float wo = w + o;
        float d2 = wo - kt;
        float e2 = __expf(-fabsf(d2));
        bool g2  = (d2 >= 0.f);
        float A2 = g2 ? 1.f : e2;
        float B2 = g2 ? e2 : 1.f;
        p = fmaf(A2, p, B2 * vt);
        q = fmaf(A2, q, B2);
        o = g2 ? wo : kt;
    }
}

// ---------------- launch ----------------
extern "C" void kernel_launch(void* const* d_in, const int* in_sizes, int n_in,
                              void* d_out, int out_size) {
    const float* x       = (const float*)d_in[0];
    const float* W_key   = (const float*)d_in[1];
    const float* W_value = (const float*)d_in[2];
    const float* W_recep = (const float*)d_in[3];
    const float* W_out   = (const float*)d_in[4];
    const float* decay   = (const float*)d_in[5];
    const float* first   = (const float*)d_in[6];
    float* out = (float*)d_out;

    float *v;
    __half *kh, *srh, *a, *w;
    cudaGetSymbolAddress((void**)&kh,  g_kh);
    cudaGetSymbolAddress((void**)&v,   g_v);
    cudaGetSymbolAddress((void**)&srh, g_srh);
    cudaGetSymbolAddress((void**)&a,   g_a);
    cudaGetSymbolAddress((void**)&w,   g_w);

    cudaFuncSetAttribute(gemm3_f16, cudaFuncAttributeMaxDynamicSharedMemorySize, SM_TOT);
    cudaFuncSetAttribute(gemm1_f16, cudaFuncAttributeMaxDynamicSharedMemorySize, SM_TOT);

    dim3 eb(256), eg(BTC / 4 / 256);
    dim3 cg(4 * CC * CC / 256);
    dim3 gb(256), gg3(12, GM / 128), gg1(4, GM / 128);
    dim3 wb(1024), wg(BB * (CC / CPB));

    shift_zigzag_f16<<<eg, eb>>>(x, a);
    conv_w4<<<cg, eb>>>(W_key, W_value, W_recep, W_out, w);
    gemm3_f16<<<gg3, gb, SM_TOT>>>(a, w, kh, v, srh);
    wkv1<<<wg, wb>>>(decay, first, kh, v, v);
    wkv2<<<wg, wb>>>(decay, first, kh, v, srh, a);
    gemm1_f16<<<gg1, gb, SM_TOT>>>(a, w + 3 * (size_t)CC * CC, out);
}